// round 4
// baseline (speedup 1.0000x reference)
#include <cuda_runtime.h>
#include <math.h>

// ---------------- problem constants (fixed-shape problem) ----------------
#define NN 100000
#define EE 3200000
#define F_IN 128
#define HID 64
#define NLAYER 64
#define NCLASS 47
#define ALPHA 0.1f
#define THETA 0.5f

// ---------------- scratch (static device globals; no allocation) ---------
__device__ __align__(16) float g_x0[NN * HID];   // relu(x@W1+b1)
__device__ __align__(16) float g_hA[NN * HID];   // ping
__device__ __align__(16) float g_hB[NN * HID];   // pong
__device__ int   g_rowptr[NN + 1];
__device__ int   g_cnt[NN];
__device__ int   g_cursor[NN];
__device__ int   g_col[EE];
__device__ float g_dinv[NN];
__device__ int   g_bsum[128];
__device__ int   g_is64;        // 1 if edge_index buffer is int64, 0 if int32

__device__ __forceinline__ const float* pick_buf(int s) {
    return (s == 0) ? g_x0 : ((s == 1) ? g_hA : g_hB);
}
__device__ __forceinline__ float* pick_buf_mut(int s) {
    return (s == 1) ? g_hA : g_hB;
}

// ---------------- edge dtype detection ----------------
// If int64 (values < 2^32, little-endian): odd 32-bit words of the first 64
// entries are all zero. If int32 uniform in [0, 100000): P(all zero) ~ 0.
__global__ void detect_kernel(const unsigned int* __restrict__ p) {
    if (threadIdx.x == 0 && blockIdx.x == 0) {
        int all0 = 1;
        for (int i = 0; i < 64; i++) {
            if (p[2 * i + 1] != 0u) { all0 = 0; break; }
        }
        g_is64 = all0;
    }
}

__device__ __forceinline__ int edge_at(const void* eiv, size_t idx, int is64) {
    if (is64) return (int)((const long long*)eiv)[idx];
    return ((const int*)eiv)[idx];
}

// ---------------- CSR construction ----------------
__global__ void zero_cnt_kernel() {
    int i = blockIdx.x * blockDim.x + threadIdx.x;
    if (i < NN) g_cnt[i] = 0;
}

__global__ void count_kernel(const void* __restrict__ eiv) {
    int i = blockIdx.x * blockDim.x + threadIdx.x;
    int is64 = g_is64;
    if (i < EE) {
        int dst = edge_at(eiv, (size_t)EE + i, is64);
        atomicAdd(&g_cnt[dst], 1);
    }
}

// block-level exclusive scan over 1024 elements (256 thr x 4)
__global__ void scan1_kernel() {
    __shared__ int sh[256];
    int t = threadIdx.x, b = blockIdx.x;
    int base = b * 1024 + t * 4;
    int v0 = (base + 0 < NN) ? g_cnt[base + 0] : 0;
    int v1 = (base + 1 < NN) ? g_cnt[base + 1] : 0;
    int v2 = (base + 2 < NN) ? g_cnt[base + 2] : 0;
    int v3 = (base + 3 < NN) ? g_cnt[base + 3] : 0;
    int s0 = v0, s1 = s0 + v1, s2 = s1 + v2, s3 = s2 + v3;
    sh[t] = s3;
    __syncthreads();
    for (int off = 1; off < 256; off <<= 1) {
        int v = (t >= off) ? sh[t - off] : 0;
        __syncthreads();
        sh[t] += v;
        __syncthreads();
    }
    int excl = sh[t] - s3;
    if (base + 0 < NN) g_rowptr[base + 0] = excl;
    if (base + 1 < NN) g_rowptr[base + 1] = excl + s0;
    if (base + 2 < NN) g_rowptr[base + 2] = excl + s1;
    if (base + 3 < NN) g_rowptr[base + 3] = excl + s2;
    if (t == 255) g_bsum[b] = sh[255];
}

__global__ void scan2_kernel(int nblk) {
    if (threadIdx.x == 0 && blockIdx.x == 0) {
        int run = 0;
        for (int b = 0; b < nblk; b++) {
            int v = g_bsum[b];
            g_bsum[b] = run;
            run += v;
        }
        g_rowptr[NN] = run;  // == EE
    }
}

__global__ void scan3_kernel() {
    int i = blockIdx.x * blockDim.x + threadIdx.x;
    if (i < NN) {
        int rp = g_rowptr[i] + g_bsum[i >> 10];
        g_rowptr[i] = rp;
        g_cursor[i] = rp;
        g_dinv[i] = rsqrtf((float)(g_cnt[i] + 1));  // +1 self loop
    }
}

__global__ void scatter_kernel(const void* __restrict__ eiv) {
    int i = blockIdx.x * blockDim.x + threadIdx.x;
    int is64 = g_is64;
    if (i < EE) {
        int src = edge_at(eiv, (size_t)i, is64);
        int dst = edge_at(eiv, (size_t)EE + i, is64);
        int pos = atomicAdd(&g_cursor[dst], 1);
        g_col[pos] = src;
    }
}

// ---------------- x0 = relu(x @ W1 + b1) ----------------
__global__ void __launch_bounds__(256) x0_kernel(const float* __restrict__ x,
                                                 const float* __restrict__ W1,
                                                 const float* __restrict__ b1) {
    __shared__ __align__(16) float Ws[F_IN * HID];  // 32KB
    int tid = threadIdx.x;
    const float4* W4 = (const float4*)W1;
    float4* Ws4 = (float4*)Ws;
#pragma unroll
    for (int i = tid; i < (F_IN * HID) / 4; i += 256) Ws4[i] = W4[i];
    __syncthreads();

    int base = blockIdx.x * 64;
    int w = tid >> 5, lane = tid & 31;
    float bx = b1[2 * lane], by = b1[2 * lane + 1];
#pragma unroll 1
    for (int i = 0; i < 8; i++) {
        int r = base + w * 8 + i;
        if (r >= NN) continue;
        float ax = bx, ay = by;
        const float4* xr = (const float4*)(x + (size_t)r * F_IN);
#pragma unroll 8
        for (int kk = 0; kk < F_IN / 4; kk++) {
            float4 xv = xr[kk];
            int k = kk * 4;
            float2 w0 = ((const float2*)(Ws + (k + 0) * HID))[lane];
            float2 w1 = ((const float2*)(Ws + (k + 1) * HID))[lane];
            float2 w2 = ((const float2*)(Ws + (k + 2) * HID))[lane];
            float2 w3 = ((const float2*)(Ws + (k + 3) * HID))[lane];
            ax += xv.x * w0.x; ay += xv.x * w0.y;
            ax += xv.y * w1.x; ay += xv.y * w1.y;
            ax += xv.z * w2.x; ay += xv.z * w2.y;
            ax += xv.w * w3.x; ay += xv.w * w3.y;
        }
        float2 v = make_float2(fmaxf(ax, 0.f), fmaxf(ay, 0.f));
        ((float2*)(g_x0 + (size_t)r * HID))[lane] = v;
    }
}

// ---------------- fused layer: SPMM + residual mix + (1-b)s + b*(s@W) + relu
__global__ void __launch_bounds__(256) layer_kernel(const float* __restrict__ Wl,
                                                    float beta, int sel_in, int sel_out) {
    __shared__ __align__(16) float Ws[HID * HID];    // 16KB
    __shared__ __align__(16) float ss[64 * 65];      // 16.6KB, pitch 65
    const float* __restrict__ hin = pick_buf(sel_in);
    float* __restrict__ hout = pick_buf_mut(sel_out);

    int tid = threadIdx.x;
    {   // stage Wl
        const float4* W4 = (const float4*)Wl;
        float4* Ws4 = (float4*)Ws;
#pragma unroll
        for (int i = tid; i < (HID * HID) / 4; i += 256) Ws4[i] = W4[i];
    }

    int base = blockIdx.x * 64;
    int w = tid >> 5, lane = tid & 31;

    // -------- phase 1: warp-per-row gather --------
#pragma unroll 1
    for (int i = 0; i < 8; i++) {
        int rl = w * 8 + i;
        int r = base + rl;
        float sx = 0.f, sy = 0.f;
        if (r < NN) {
            float dr = g_dinv[r];
            float2 hv = ((const float2*)(hin + (size_t)r * HID))[lane];
            float wself = dr * dr;
            float ax = wself * hv.x, ay = wself * hv.y;
            int e = g_rowptr[r];
            int e1 = g_rowptr[r + 1];
            for (; e + 4 <= e1; e += 4) {
                int c0 = g_col[e + 0];
                int c1 = g_col[e + 1];
                int c2 = g_col[e + 2];
                int c3 = g_col[e + 3];
                float w0 = dr * g_dinv[c0];
                float w1 = dr * g_dinv[c1];
                float w2 = dr * g_dinv[c2];
                float w3 = dr * g_dinv[c3];
                float2 h0 = ((const float2*)(hin + (size_t)c0 * HID))[lane];
                float2 h1 = ((const float2*)(hin + (size_t)c1 * HID))[lane];
                float2 h2 = ((const float2*)(hin + (size_t)c2 * HID))[lane];
                float2 h3 = ((const float2*)(hin + (size_t)c3 * HID))[lane];
                ax += w0 * h0.x; ay += w0 * h0.y;
                ax += w1 * h1.x; ay += w1 * h1.y;
                ax += w2 * h2.x; ay += w2 * h2.y;
                ax += w3 * h3.x; ay += w3 * h3.y;
            }
            for (; e < e1; e++) {
                int c = g_col[e];
                float wv = dr * g_dinv[c];
                float2 h0 = ((const float2*)(hin + (size_t)c * HID))[lane];
                ax += wv * h0.x; ay += wv * h0.y;
            }
            float2 x0v = ((const float2*)(g_x0 + (size_t)r * HID))[lane];
            sx = (1.f - ALPHA) * ax + ALPHA * x0v.x;
            sy = (1.f - ALPHA) * ay + ALPHA * x0v.y;
        }
        ss[rl * 65 + 2 * lane + 0] = sx;
        ss[rl * 65 + 2 * lane + 1] = sy;
    }
    __syncthreads();

    // -------- phase 2: 64x64 @ 64x64 GEMM from shared --------
    int rl = tid & 63;
    int gq = tid >> 6;          // 4 groups of 16 columns
    int cbase = gq * 16;
    float acc[16];
#pragma unroll
    for (int i = 0; i < 16; i++) acc[i] = 0.f;
#pragma unroll 4
    for (int k = 0; k < HID; k++) {
        float sk = ss[rl * 65 + k];
        const float4* wr = (const float4*)(Ws + k * HID + cbase);  // warp-uniform -> broadcast
        float4 a = wr[0], b = wr[1], c = wr[2], d = wr[3];
        acc[0] += sk * a.x;  acc[1] += sk * a.y;  acc[2] += sk * a.z;  acc[3] += sk * a.w;
        acc[4] += sk * b.x;  acc[5] += sk * b.y;  acc[6] += sk * b.z;  acc[7] += sk * b.w;
        acc[8] += sk * c.x;  acc[9] += sk * c.y;  acc[10] += sk * c.z; acc[11] += sk * c.w;
        acc[12] += sk * d.x; acc[13] += sk * d.y; acc[14] += sk * d.z; acc[15] += sk * d.w;
    }
    int r = base + rl;
    if (r < NN) {
        float ob = 1.f - beta;
        float4* op = (float4*)(hout + (size_t)r * HID + cbase);
#pragma unroll
        for (int q = 0; q < 4; q++) {
            float v0 = fmaxf(ob * ss[rl * 65 + cbase + 4 * q + 0] + beta * acc[4 * q + 0], 0.f);
            float v1 = fmaxf(ob * ss[rl * 65 + cbase + 4 * q + 1] + beta * acc[4 * q + 1], 0.f);
            float v2 = fmaxf(ob * ss[rl * 65 + cbase + 4 * q + 2] + beta * acc[4 * q + 2], 0.f);
            float v3 = fmaxf(ob * ss[rl * 65 + cbase + 4 * q + 3] + beta * acc[4 * q + 3], 0.f);
            op[q] = make_float4(v0, v1, v2, v3);
        }
    }
}

// ---------------- logits + log_softmax ----------------
__global__ void __launch_bounds__(256) out_kernel(int sel_in,
                                                  const float* __restrict__ W2,
                                                  const float* __restrict__ b2,
                                                  float* __restrict__ out) {
    __shared__ float W2s[HID * NCLASS];
    __shared__ float b2s[NCLASS];
    __shared__ float hrow[8][HID];
    const float* __restrict__ hin = pick_buf(sel_in);

    int tid = threadIdx.x;
    for (int i = tid; i < HID * NCLASS; i += 256) W2s[i] = W2[i];
    if (tid < NCLASS) b2s[tid] = b2[tid];
    __syncthreads();

    int w = tid >> 5, lane = tid & 31;
    int r = blockIdx.x * 8 + w;
    if (r < NN) {
        hrow[w][lane] = hin[(size_t)r * HID + lane];
        hrow[w][lane + 32] = hin[(size_t)r * HID + lane + 32];
    }
    __syncwarp();
    if (r >= NN) return;

    int j0 = lane, j1 = lane + 32;
    bool has1 = (j1 < NCLASS);
    float a0 = b2s[j0];
    float a1 = has1 ? b2s[j1] : 0.f;
#pragma unroll 4
    for (int k = 0; k < HID; k++) {
        float hv = hrow[w][k];
        a0 += hv * W2s[k * NCLASS + j0];
        if (has1) a1 += hv * W2s[k * NCLASS + j1];
    }
    float m = a0;
    if (has1) m = fmaxf(m, a1);
#pragma unroll
    for (int off = 16; off; off >>= 1) m = fmaxf(m, __shfl_xor_sync(0xffffffffu, m, off));
    float s = expf(a0 - m) + (has1 ? expf(a1 - m) : 0.f);
#pragma unroll
    for (int off = 16; off; off >>= 1) s += __shfl_xor_sync(0xffffffffu, s, off);
    float lse = m + logf(s);
    out[(size_t)r * NCLASS + j0] = a0 - lse;
    if (has1) out[(size_t)r * NCLASS + j1] = a1 - lse;
}

// ---------------- launch ----------------
extern "C" void kernel_launch(void* const* d_in, const int* in_sizes, int n_in,
                              void* d_out, int out_size) {
    const float* x = (const float*)d_in[0];
    const void* ei = (const void*)d_in[1];
    const float* W1 = (const float*)d_in[2];
    const float* b1 = (const float*)d_in[3];
    const float* convW = (const float*)d_in[4];
    const float* W2 = (const float*)d_in[5];
    const float* b2 = (const float*)d_in[6];
    float* out = (float*)d_out;

    const int TB = 256;
    const int nblkN = (NN + TB - 1) / TB;
    const int nblkE = (EE + TB - 1) / TB;
    const int nscan = (NN + 1023) / 1024;      // 98
    const int nrowblk = (NN + 63) / 64;        // 1563

    // detect edge_index element width (int32 vs int64), then build CSR
    detect_kernel<<<1, 32>>>((const unsigned int*)ei);
    zero_cnt_kernel<<<nblkN, TB>>>();
    count_kernel<<<nblkE, TB>>>(ei);
    scan1_kernel<<<nscan, TB>>>();
    scan2_kernel<<<1, 32>>>(nscan);
    scan3_kernel<<<nblkN, TB>>>();
    scatter_kernel<<<nblkE, TB>>>(ei);

    // x0
    x0_kernel<<<nrowblk, TB>>>(x, W1, b1);

    // 64 fused layers (ping-pong: x0 -> A -> B -> A -> ...)
    int sel_in = 0;
    for (int l = 0; l < NLAYER; l++) {
        float beta = logf(THETA / (float)(l + 1) + 1.0f);
        int sel_out = (l & 1) ? 2 : 1;
        layer_kernel<<<nrowblk, TB>>>(convW + (size_t)l * HID * HID, beta, sel_in, sel_out);
        sel_in = sel_out;
    }

    // logits + log_softmax (last layer l=63 wrote buffer B -> sel_in==2)
    out_kernel<<<(NN + 7) / 8, TB>>>(sel_in, W2, b2, out);
}

// round 5
// speedup vs baseline: 1.2816x; 1.2816x over previous
#include <cuda_runtime.h>
#include <cuda_fp16.h>
#include <math.h>

// ---------------- problem constants (fixed-shape problem) ----------------
#define NN 100000
#define EE 3200000
#define F_IN 128
#define HID 64
#define NLAYER 64
#define NCLASS 47
#define ALPHA 0.1f
#define THETA 0.5f

// ---------------- scratch (static device globals; no allocation) ---------
__device__ __align__(16) float  g_x0[NN * HID];   // relu(x@W1+b1), fp32 residual
__device__ __align__(16) __half g_hA[NN * HID];   // ping (fp16 feature rows)
__device__ __align__(16) __half g_hB[NN * HID];   // pong
__device__ __align__(16) int2   g_colw[EE];       // packed {col, weight bits}
__device__ int   g_rowptr[NN + 1];
__device__ int   g_cnt[NN];
__device__ int   g_cursor[NN];
__device__ float g_dinv[NN];
__device__ int   g_bsum[128];
__device__ int   g_is64;        // 1 if edge_index buffer is int64, 0 if int32

__device__ __forceinline__ const __half* pick_half(int s) {
    return (s == 1) ? g_hA : g_hB;
}
__device__ __forceinline__ __half* pick_half_mut(int s) {
    return (s == 1) ? g_hA : g_hB;
}

// ---------------- edge dtype detection ----------------
__global__ void detect_kernel(const unsigned int* __restrict__ p) {
    if (threadIdx.x == 0 && blockIdx.x == 0) {
        int all0 = 1;
        for (int i = 0; i < 64; i++) {
            if (p[2 * i + 1] != 0u) { all0 = 0; break; }
        }
        g_is64 = all0;
    }
}

__device__ __forceinline__ int edge_at(const void* eiv, size_t idx, int is64) {
    if (is64) return (int)((const long long*)eiv)[idx];
    return ((const int*)eiv)[idx];
}

// ---------------- CSR construction ----------------
__global__ void zero_cnt_kernel() {
    int i = blockIdx.x * blockDim.x + threadIdx.x;
    if (i < NN) g_cnt[i] = 0;
}

__global__ void count_kernel(const void* __restrict__ eiv) {
    int i = blockIdx.x * blockDim.x + threadIdx.x;
    int is64 = g_is64;
    if (i < EE) {
        int dst = edge_at(eiv, (size_t)EE + i, is64);
        atomicAdd(&g_cnt[dst], 1);
    }
}

// block-level exclusive scan over 1024 elements (256 thr x 4)
__global__ void scan1_kernel() {
    __shared__ int sh[256];
    int t = threadIdx.x, b = blockIdx.x;
    int base = b * 1024 + t * 4;
    int v0 = (base + 0 < NN) ? g_cnt[base + 0] : 0;
    int v1 = (base + 1 < NN) ? g_cnt[base + 1] : 0;
    int v2 = (base + 2 < NN) ? g_cnt[base + 2] : 0;
    int v3 = (base + 3 < NN) ? g_cnt[base + 3] : 0;
    int s0 = v0, s1 = s0 + v1, s2 = s1 + v2, s3 = s2 + v3;
    sh[t] = s3;
    __syncthreads();
    for (int off = 1; off < 256; off <<= 1) {
        int v = (t >= off) ? sh[t - off] : 0;
        __syncthreads();
        sh[t] += v;
        __syncthreads();
    }
    int excl = sh[t] - s3;
    if (base + 0 < NN) g_rowptr[base + 0] = excl;
    if (base + 1 < NN) g_rowptr[base + 1] = excl + s0;
    if (base + 2 < NN) g_rowptr[base + 2] = excl + s1;
    if (base + 3 < NN) g_rowptr[base + 3] = excl + s2;
    if (t == 255) g_bsum[b] = sh[255];
}

__global__ void scan2_kernel(int nblk) {
    if (threadIdx.x == 0 && blockIdx.x == 0) {
        int run = 0;
        for (int b = 0; b < nblk; b++) {
            int v = g_bsum[b];
            g_bsum[b] = run;
            run += v;
        }
        g_rowptr[NN] = run;  // == EE
    }
}

__global__ void scan3_kernel() {
    int i = blockIdx.x * blockDim.x + threadIdx.x;
    if (i < NN) {
        int rp = g_rowptr[i] + g_bsum[i >> 10];
        g_rowptr[i] = rp;
        g_cursor[i] = rp;
        g_dinv[i] = rsqrtf((float)(g_cnt[i] + 1));  // +1 self loop
    }
}

// scatter edges AND bake layer-invariant weight dinv[dst]*dinv[src] into 8B slot
__global__ void scatter_kernel(const void* __restrict__ eiv) {
    int i = blockIdx.x * blockDim.x + threadIdx.x;
    int is64 = g_is64;
    if (i < EE) {
        int src = edge_at(eiv, (size_t)i, is64);
        int dst = edge_at(eiv, (size_t)EE + i, is64);
        int pos = atomicAdd(&g_cursor[dst], 1);
        float w = g_dinv[dst] * g_dinv[src];
        g_colw[pos] = make_int2(src, __float_as_int(w));
    }
}

// ---------------- x0 = relu(x @ W1 + b1); also seed fp16 copy in g_hA ----
__global__ void __launch_bounds__(256) x0_kernel(const float* __restrict__ x,
                                                 const float* __restrict__ W1,
                                                 const float* __restrict__ b1) {
    __shared__ __align__(16) float Ws[F_IN * HID];  // 32KB
    int tid = threadIdx.x;
    const float4* W4 = (const float4*)W1;
    float4* Ws4 = (float4*)Ws;
#pragma unroll
    for (int i = tid; i < (F_IN * HID) / 4; i += 256) Ws4[i] = W4[i];
    __syncthreads();

    int base = blockIdx.x * 64;
    int w = tid >> 5, lane = tid & 31;
    float bx = b1[2 * lane], by = b1[2 * lane + 1];
#pragma unroll 1
    for (int i = 0; i < 8; i++) {
        int r = base + w * 8 + i;
        if (r >= NN) continue;
        float ax = bx, ay = by;
        const float4* xr = (const float4*)(x + (size_t)r * F_IN);
#pragma unroll 8
        for (int kk = 0; kk < F_IN / 4; kk++) {
            float4 xv = xr[kk];
            int k = kk * 4;
            float2 w0 = ((const float2*)(Ws + (k + 0) * HID))[lane];
            float2 w1 = ((const float2*)(Ws + (k + 1) * HID))[lane];
            float2 w2 = ((const float2*)(Ws + (k + 2) * HID))[lane];
            float2 w3 = ((const float2*)(Ws + (k + 3) * HID))[lane];
            ax += xv.x * w0.x; ay += xv.x * w0.y;
            ax += xv.y * w1.x; ay += xv.y * w1.y;
            ax += xv.z * w2.x; ay += xv.z * w2.y;
            ax += xv.w * w3.x; ay += xv.w * w3.y;
        }
        float vx = fmaxf(ax, 0.f), vy = fmaxf(ay, 0.f);
        ((float2*)(g_x0 + (size_t)r * HID))[lane] = make_float2(vx, vy);
        ((__half2*)(g_hA + (size_t)r * HID))[lane] = __floats2half2_rn(vx, vy);
    }
}

// ---------------- fused layer: SPMM(fp16 gather) + mix + (1-b)s + b*(s@W) + relu
__global__ void __launch_bounds__(256) layer_kernel(const float* __restrict__ Wl,
                                                    float beta, int sel_in, int sel_out) {
    __shared__ __align__(16) float Ws[HID * HID];    // 16KB
    __shared__ __align__(16) float ss[64 * 65];      // 16.6KB, pitch 65
    const __half* __restrict__ hin = pick_half(sel_in);
    __half* __restrict__ hout = pick_half_mut(sel_out);

    int tid = threadIdx.x;
    {   // stage Wl
        const float4* W4 = (const float4*)Wl;
        float4* Ws4 = (float4*)Ws;
#pragma unroll
        for (int i = tid; i < (HID * HID) / 4; i += 256) Ws4[i] = W4[i];
    }

    int base = blockIdx.x * 64;
    int w = tid >> 5, lane = tid & 31;

    // -------- phase 1: warp-per-row gather (chain: colw -> h, MLP=8) --------
#pragma unroll 1
    for (int i = 0; i < 8; i++) {
        int rl = w * 8 + i;
        int r = base + rl;
        float sx = 0.f, sy = 0.f;
        if (r < NN) {
            float dr = g_dinv[r];
            float2 hv = __half22float2(((const __half2*)(hin + (size_t)r * HID))[lane]);
            float wself = dr * dr;
            float ax = wself * hv.x, ay = wself * hv.y;
            int e = g_rowptr[r];
            int e1 = g_rowptr[r + 1];
            for (; e + 8 <= e1; e += 8) {
                int2 cw[8];
#pragma unroll
                for (int j = 0; j < 8; j++) cw[j] = g_colw[e + j];
                __half2 hh[8];
#pragma unroll
                for (int j = 0; j < 8; j++)
                    hh[j] = ((const __half2*)(hin + (size_t)cw[j].x * HID))[lane];
#pragma unroll
                for (int j = 0; j < 8; j++) {
                    float wj = __int_as_float(cw[j].y);
                    float2 f = __half22float2(hh[j]);
                    ax += wj * f.x; ay += wj * f.y;
                }
            }
            for (; e < e1; e++) {
                int2 cwv = g_colw[e];
                float wv = __int_as_float(cwv.y);
                float2 f = __half22float2(((const __half2*)(hin + (size_t)cwv.x * HID))[lane]);
                ax += wv * f.x; ay += wv * f.y;
            }
            float2 x0v = ((const float2*)(g_x0 + (size_t)r * HID))[lane];
            sx = (1.f - ALPHA) * ax + ALPHA * x0v.x;
            sy = (1.f - ALPHA) * ay + ALPHA * x0v.y;
        }
        ss[rl * 65 + 2 * lane + 0] = sx;
        ss[rl * 65 + 2 * lane + 1] = sy;
    }
    __syncthreads();

    // -------- phase 2: 64x64 @ 64x64 GEMM from shared --------
    int rl = tid & 63;
    int gq = tid >> 6;          // 4 groups of 16 columns
    int cbase = gq * 16;
    float acc[16];
#pragma unroll
    for (int i = 0; i < 16; i++) acc[i] = 0.f;
#pragma unroll 8
    for (int k = 0; k < HID; k++) {
        float sk = ss[rl * 65 + k];
        const float4* wr = (const float4*)(Ws + k * HID + cbase);  // warp-uniform -> broadcast
        float4 a = wr[0], b = wr[1], c = wr[2], d = wr[3];
        acc[0] += sk * a.x;  acc[1] += sk * a.y;  acc[2] += sk * a.z;  acc[3] += sk * a.w;
        acc[4] += sk * b.x;  acc[5] += sk * b.y;  acc[6] += sk * b.z;  acc[7] += sk * b.w;
        acc[8] += sk * c.x;  acc[9] += sk * c.y;  acc[10] += sk * c.z; acc[11] += sk * c.w;
        acc[12] += sk * d.x; acc[13] += sk * d.y; acc[14] += sk * d.z; acc[15] += sk * d.w;
    }
    int r = base + rl;
    if (r < NN) {
        float ob = 1.f - beta;
        unsigned int u[8];
#pragma unroll
        for (int q = 0; q < 8; q++) {
            float v0 = fmaxf(ob * ss[rl * 65 + cbase + 2 * q + 0] + beta * acc[2 * q + 0], 0.f);
            float v1 = fmaxf(ob * ss[rl * 65 + cbase + 2 * q + 1] + beta * acc[2 * q + 1], 0.f);
            __half2 h2 = __floats2half2_rn(v0, v1);
            u[q] = *(unsigned int*)&h2;
        }
        uint4* dst = (uint4*)(hout + (size_t)r * HID + cbase);  // 32B-aligned
        dst[0] = make_uint4(u[0], u[1], u[2], u[3]);
        dst[1] = make_uint4(u[4], u[5], u[6], u[7]);
    }
}

// ---------------- logits + log_softmax ----------------
__global__ void __launch_bounds__(256) out_kernel(int sel_in,
                                                  const float* __restrict__ W2,
                                                  const float* __restrict__ b2,
                                                  float* __restrict__ out) {
    __shared__ float W2s[HID * NCLASS];
    __shared__ float b2s[NCLASS];
    __shared__ float hrow[8][HID];
    const __half* __restrict__ hin = pick_half(sel_in);

    int tid = threadIdx.x;
    for (int i = tid; i < HID * NCLASS; i += 256) W2s[i] = W2[i];
    if (tid < NCLASS) b2s[tid] = b2[tid];
    __syncthreads();

    int w = tid >> 5, lane = tid & 31;
    int r = blockIdx.x * 8 + w;
    if (r < NN) {
        hrow[w][lane] = __half2float(hin[(size_t)r * HID + lane]);
        hrow[w][lane + 32] = __half2float(hin[(size_t)r * HID + lane + 32]);
    }
    __syncwarp();
    if (r >= NN) return;

    int j0 = lane, j1 = lane + 32;
    bool has1 = (j1 < NCLASS);
    float a0 = b2s[j0];
    float a1 = has1 ? b2s[j1] : 0.f;
#pragma unroll 4
    for (int k = 0; k < HID; k++) {
        float hv = hrow[w][k];
        a0 += hv * W2s[k * NCLASS + j0];
        if (has1) a1 += hv * W2s[k * NCLASS + j1];
    }
    float m = a0;
    if (has1) m = fmaxf(m, a1);
#pragma unroll
    for (int off = 16; off; off >>= 1) m = fmaxf(m, __shfl_xor_sync(0xffffffffu, m, off));
    float s = expf(a0 - m) + (has1 ? expf(a1 - m) : 0.f);
#pragma unroll
    for (int off = 16; off; off >>= 1) s += __shfl_xor_sync(0xffffffffu, s, off);
    float lse = m + logf(s);
    out[(size_t)r * NCLASS + j0] = a0 - lse;
    if (has1) out[(size_t)r * NCLASS + j1] = a1 - lse;
}

// ---------------- launch ----------------
extern "C" void kernel_launch(void* const* d_in, const int* in_sizes, int n_in,
                              void* d_out, int out_size) {
    const float* x = (const float*)d_in[0];
    const void* ei = (const void*)d_in[1];
    const float* W1 = (const float*)d_in[2];
    const float* b1 = (const float*)d_in[3];
    const float* convW = (const float*)d_in[4];
    const float* W2 = (const float*)d_in[5];
    const float* b2 = (const float*)d_in[6];
    float* out = (float*)d_out;

    const int TB = 256;
    const int nblkN = (NN + TB - 1) / TB;
    const int nblkE = (EE + TB - 1) / TB;
    const int nscan = (NN + 1023) / 1024;      // 98
    const int nrowblk = (NN + 63) / 64;        // 1563

    // detect edge_index element width (int32 vs int64), then build CSR
    detect_kernel<<<1, 32>>>((const unsigned int*)ei);
    zero_cnt_kernel<<<nblkN, TB>>>();
    count_kernel<<<nblkE, TB>>>(ei);
    scan1_kernel<<<nscan, TB>>>();
    scan2_kernel<<<1, 32>>>(nscan);
    scan3_kernel<<<nblkN, TB>>>();
    scatter_kernel<<<nblkE, TB>>>(ei);

    // x0 (fp32 residual copy + fp16 seed in g_hA)
    x0_kernel<<<nrowblk, TB>>>(x, W1, b1);

    // 64 fused layers (ping-pong: A -> B -> A -> ...)
    int sel_in = 1;
    for (int l = 0; l < NLAYER; l++) {
        float beta = logf(THETA / (float)(l + 1) + 1.0f);
        int sel_out = 3 - sel_in;
        layer_kernel<<<nrowblk, TB>>>(convW + (size_t)l * HID * HID, beta, sel_in, sel_out);
        sel_in = sel_out;
    }

    // logits + log_softmax (l=63 wrote buffer A -> sel_in==1)
    out_kernel<<<(NN + 7) / 8, TB>>>(sel_in, W2, b2, out);
}

// round 6
// speedup vs baseline: 1.3011x; 1.0152x over previous
#include <cuda_runtime.h>
#include <cuda_fp16.h>
#include <math.h>

// ---------------- problem constants (fixed-shape problem) ----------------
#define NN 100000
#define EE 3200000
#define F_IN 128
#define HID 64
#define NLAYER 64
#define NCLASS 47
#define ALPHA 0.1f
#define THETA 0.5f

// ---------------- scratch (static device globals; no allocation) ---------
__device__ __align__(16) float  g_x0[NN * HID];   // relu(x@W1+b1), fp32 residual
__device__ __align__(16) __half g_hA[NN * HID];   // ping (fp16 feature rows)
__device__ __align__(16) __half g_hB[NN * HID];   // pong
__device__ __align__(16) int2   g_colw[EE];       // packed {col, weight bits}
__device__ int   g_rowptr[NN + 1];
__device__ int   g_cnt[NN];
__device__ int   g_cursor[NN];
__device__ float g_dinv[NN];
__device__ int   g_bsum[128];
__device__ int   g_is64;        // 1 if edge_index buffer is int64, 0 if int32

__device__ __forceinline__ const __half* pick_half(int s) {
    return (s == 1) ? g_hA : g_hB;
}
__device__ __forceinline__ __half* pick_half_mut(int s) {
    return (s == 1) ? g_hA : g_hB;
}

// ---------------- edge dtype detection ----------------
__global__ void detect_kernel(const unsigned int* __restrict__ p) {
    if (threadIdx.x == 0 && blockIdx.x == 0) {
        int all0 = 1;
        for (int i = 0; i < 64; i++) {
            if (p[2 * i + 1] != 0u) { all0 = 0; break; }
        }
        g_is64 = all0;
    }
}

__device__ __forceinline__ int edge_at(const void* eiv, size_t idx, int is64) {
    if (is64) return (int)((const long long*)eiv)[idx];
    return ((const int*)eiv)[idx];
}

// ---------------- CSR construction ----------------
__global__ void zero_cnt_kernel() {
    int i = blockIdx.x * blockDim.x + threadIdx.x;
    if (i < NN) g_cnt[i] = 0;
}

__global__ void count_kernel(const void* __restrict__ eiv) {
    int i = blockIdx.x * blockDim.x + threadIdx.x;
    int is64 = g_is64;
    if (i < EE) {
        int dst = edge_at(eiv, (size_t)EE + i, is64);
        atomicAdd(&g_cnt[dst], 1);
    }
}

// block-level exclusive scan over 1024 elements (256 thr x 4)
__global__ void scan1_kernel() {
    __shared__ int sh[256];
    int t = threadIdx.x, b = blockIdx.x;
    int base = b * 1024 + t * 4;
    int v0 = (base + 0 < NN) ? g_cnt[base + 0] : 0;
    int v1 = (base + 1 < NN) ? g_cnt[base + 1] : 0;
    int v2 = (base + 2 < NN) ? g_cnt[base + 2] : 0;
    int v3 = (base + 3 < NN) ? g_cnt[base + 3] : 0;
    int s0 = v0, s1 = s0 + v1, s2 = s1 + v2, s3 = s2 + v3;
    sh[t] = s3;
    __syncthreads();
    for (int off = 1; off < 256; off <<= 1) {
        int v = (t >= off) ? sh[t - off] : 0;
        __syncthreads();
        sh[t] += v;
        __syncthreads();
    }
    int excl = sh[t] - s3;
    if (base + 0 < NN) g_rowptr[base + 0] = excl;
    if (base + 1 < NN) g_rowptr[base + 1] = excl + s0;
    if (base + 2 < NN) g_rowptr[base + 2] = excl + s1;
    if (base + 3 < NN) g_rowptr[base + 3] = excl + s2;
    if (t == 255) g_bsum[b] = sh[255];
}

__global__ void scan2_kernel(int nblk) {
    if (threadIdx.x == 0 && blockIdx.x == 0) {
        int run = 0;
        for (int b = 0; b < nblk; b++) {
            int v = g_bsum[b];
            g_bsum[b] = run;
            run += v;
        }
        g_rowptr[NN] = run;  // == EE
    }
}

__global__ void scan3_kernel() {
    int i = blockIdx.x * blockDim.x + threadIdx.x;
    if (i < NN) {
        int rp = g_rowptr[i] + g_bsum[i >> 10];
        g_rowptr[i] = rp;
        g_cursor[i] = rp;
        g_dinv[i] = rsqrtf((float)(g_cnt[i] + 1));  // +1 self loop
    }
}

// scatter edges AND bake layer-invariant weight dinv[dst]*dinv[src] into 8B slot
__global__ void scatter_kernel(const void* __restrict__ eiv) {
    int i = blockIdx.x * blockDim.x + threadIdx.x;
    int is64 = g_is64;
    if (i < EE) {
        int src = edge_at(eiv, (size_t)i, is64);
        int dst = edge_at(eiv, (size_t)EE + i, is64);
        int pos = atomicAdd(&g_cursor[dst], 1);
        float w = g_dinv[dst] * g_dinv[src];
        g_colw[pos] = make_int2(src, __float_as_int(w));
    }
}

// ---------------- x0 = relu(x @ W1 + b1); also seed fp16 copy in g_hA ----
__global__ void __launch_bounds__(256) x0_kernel(const float* __restrict__ x,
                                                 const float* __restrict__ W1,
                                                 const float* __restrict__ b1) {
    __shared__ __align__(16) float Ws[F_IN * HID];  // 32KB
    int tid = threadIdx.x;
    const float4* W4 = (const float4*)W1;
    float4* Ws4 = (float4*)Ws;
#pragma unroll
    for (int i = tid; i < (F_IN * HID) / 4; i += 256) Ws4[i] = W4[i];
    __syncthreads();

    int base = blockIdx.x * 64;
    int w = tid >> 5, lane = tid & 31;
    float bx = b1[2 * lane], by = b1[2 * lane + 1];
#pragma unroll 1
    for (int i = 0; i < 8; i++) {
        int r = base + w * 8 + i;
        if (r >= NN) continue;
        float ax = bx, ay = by;
        const float4* xr = (const float4*)(x + (size_t)r * F_IN);
#pragma unroll 8
        for (int kk = 0; kk < F_IN / 4; kk++) {
            float4 xv = xr[kk];
            int k = kk * 4;
            float2 w0 = ((const float2*)(Ws + (k + 0) * HID))[lane];
            float2 w1 = ((const float2*)(Ws + (k + 1) * HID))[lane];
            float2 w2 = ((const float2*)(Ws + (k + 2) * HID))[lane];
            float2 w3 = ((const float2*)(Ws + (k + 3) * HID))[lane];
            ax += xv.x * w0.x; ay += xv.x * w0.y;
            ax += xv.y * w1.x; ay += xv.y * w1.y;
            ax += xv.z * w2.x; ay += xv.z * w2.y;
            ax += xv.w * w3.x; ay += xv.w * w3.y;
        }
        float vx = fmaxf(ax, 0.f), vy = fmaxf(ay, 0.f);
        ((float2*)(g_x0 + (size_t)r * HID))[lane] = make_float2(vx, vy);
        ((__half2*)(g_hA + (size_t)r * HID))[lane] = __floats2half2_rn(vx, vy);
    }
}

// ---------------- fused layer: SPMM(fp16 gather) + mix + (1-b)s + b*(s@W) + relu
__global__ void __launch_bounds__(256) layer_kernel(const float* __restrict__ Wl,
                                                    float beta, int sel_in, int sel_out) {
    __shared__ __align__(16) float Ws[HID * HID];    // 16KB
    __shared__ __align__(16) float ss[64 * 65];      // 16.6KB, pitch 65
    const __half* __restrict__ hin = pick_half(sel_in);
    __half* __restrict__ hout = pick_half_mut(sel_out);

    int tid = threadIdx.x;
    {   // stage Wl
        const float4* W4 = (const float4*)Wl;
        float4* Ws4 = (float4*)Ws;
#pragma unroll
        for (int i = tid; i < (HID * HID) / 4; i += 256) Ws4[i] = W4[i];
    }

    int base = blockIdx.x * 64;
    int w = tid >> 5, lane = tid & 31;

    // -------- phase 1: warp-per-row gather --------
    // Per 32-edge chunk: one coalesced lane-parallel colw load (lanes >= rem
    // hold {col=0, w=0} so padded loads are harmless, L2-hot, contribute 0).
    // h-row loads are double-buffered in groups of 8: issue next group's
    // loads before consuming the previous group -> L2 latency exposed once
    // per row, not once per group.
#pragma unroll 1
    for (int i = 0; i < 8; i++) {
        int rl = w * 8 + i;
        int r = base + rl;
        float sx = 0.f, sy = 0.f;
        if (r < NN) {
            float dr = g_dinv[r];
            float2 hv = __half22float2(((const __half2*)(hin + (size_t)r * HID))[lane]);
            float wself = dr * dr;
            float ax = wself * hv.x, ay = wself * hv.y;
            int e = g_rowptr[r];
            const int e1 = g_rowptr[r + 1];
#pragma unroll 1
            while (e < e1) {
                int rem = e1 - e;
                int2 cw = make_int2(0, 0);
                if (lane < rem) cw = g_colw[e + lane];
                int ng = rem < 32 ? rem : 32;

                __half2 ha[8];
#pragma unroll
                for (int q = 0; q < 8; q++) {
                    int c = __shfl_sync(0xffffffffu, cw.x, q);
                    ha[q] = ((const __half2*)(hin + (size_t)c * HID))[lane];
                }
                int jprev = 0;
#pragma unroll 1
                for (int j = 8; j < ng; j += 8) {
                    __half2 hb[8];
#pragma unroll
                    for (int q = 0; q < 8; q++) {
                        int c = __shfl_sync(0xffffffffu, cw.x, j + q);
                        hb[q] = ((const __half2*)(hin + (size_t)c * HID))[lane];
                    }
#pragma unroll
                    for (int q = 0; q < 8; q++) {
                        float wq = __int_as_float(__shfl_sync(0xffffffffu, cw.y, jprev + q));
                        float2 f = __half22float2(ha[q]);
                        ax += wq * f.x; ay += wq * f.y;
                    }
#pragma unroll
                    for (int q = 0; q < 8; q++) ha[q] = hb[q];
                    jprev = j;
                }
#pragma unroll
                for (int q = 0; q < 8; q++) {
                    float wq = __int_as_float(__shfl_sync(0xffffffffu, cw.y, jprev + q));
                    float2 f = __half22float2(ha[q]);
                    ax += wq * f.x; ay += wq * f.y;
                }
                e += 32;
            }
            float2 x0v = ((const float2*)(g_x0 + (size_t)r * HID))[lane];
            sx = (1.f - ALPHA) * ax + ALPHA * x0v.x;
            sy = (1.f - ALPHA) * ay + ALPHA * x0v.y;
        }
        ss[rl * 65 + 2 * lane + 0] = sx;
        ss[rl * 65 + 2 * lane + 1] = sy;
    }
    __syncthreads();

    // -------- phase 2: 64x64 @ 64x64 GEMM from shared --------
    int rl = tid & 63;
    int gq = tid >> 6;          // 4 groups of 16 columns
    int cbase = gq * 16;
    float acc[16];
#pragma unroll
    for (int i = 0; i < 16; i++) acc[i] = 0.f;
#pragma unroll 8
    for (int k = 0; k < HID; k++) {
        float sk = ss[rl * 65 + k];
        const float4* wr = (const float4*)(Ws + k * HID + cbase);  // warp-uniform -> broadcast
        float4 a = wr[0], b = wr[1], c = wr[2], d = wr[3];
        acc[0] += sk * a.x;  acc[1] += sk * a.y;  acc[2] += sk * a.z;  acc[3] += sk * a.w;
        acc[4] += sk * b.x;  acc[5] += sk * b.y;  acc[6] += sk * b.z;  acc[7] += sk * b.w;
        acc[8] += sk * c.x;  acc[9] += sk * c.y;  acc[10] += sk * c.z; acc[11] += sk * c.w;
        acc[12] += sk * d.x; acc[13] += sk * d.y; acc[14] += sk * d.z; acc[15] += sk * d.w;
    }
    int r = base + rl;
    if (r < NN) {
        float ob = 1.f - beta;
        unsigned int u[8];
#pragma unroll
        for (int q = 0; q < 8; q++) {
            float v0 = fmaxf(ob * ss[rl * 65 + cbase + 2 * q + 0] + beta * acc[2 * q + 0], 0.f);
            float v1 = fmaxf(ob * ss[rl * 65 + cbase + 2 * q + 1] + beta * acc[2 * q + 1], 0.f);
            __half2 h2 = __floats2half2_rn(v0, v1);
            u[q] = *(unsigned int*)&h2;
        }
        uint4* dst = (uint4*)(hout + (size_t)r * HID + cbase);  // 32B-aligned
        dst[0] = make_uint4(u[0], u[1], u[2], u[3]);
        dst[1] = make_uint4(u[4], u[5], u[6], u[7]);
    }
}

// ---------------- logits + log_softmax ----------------
__global__ void __launch_bounds__(256) out_kernel(int sel_in,
                                                  const float* __restrict__ W2,
                                                  const float* __restrict__ b2,
                                                  float* __restrict__ out) {
    __shared__ float W2s[HID * NCLASS];
    __shared__ float b2s[NCLASS];
    __shared__ float hrow[8][HID];
    const __half* __restrict__ hin = pick_half(sel_in);

    int tid = threadIdx.x;
    for (int i = tid; i < HID * NCLASS; i += 256) W2s[i] = W2[i];
    if (tid < NCLASS) b2s[tid] = b2[tid];
    __syncthreads();

    int w = tid >> 5, lane = tid & 31;
    int r = blockIdx.x * 8 + w;
    if (r < NN) {
        hrow[w][lane] = __half2float(hin[(size_t)r * HID + lane]);
        hrow[w][lane + 32] = __half2float(hin[(size_t)r * HID + lane + 32]);
    }
    __syncwarp();
    if (r >= NN) return;

    int j0 = lane, j1 = lane + 32;
    bool has1 = (j1 < NCLASS);
    float a0 = b2s[j0];
    float a1 = has1 ? b2s[j1] : 0.f;
#pragma unroll 4
    for (int k = 0; k < HID; k++) {
        float hv = hrow[w][k];
        a0 += hv * W2s[k * NCLASS + j0];
        if (has1) a1 += hv * W2s[k * NCLASS + j1];
    }
    float m = a0;
    if (has1) m = fmaxf(m, a1);
#pragma unroll
    for (int off = 16; off; off >>= 1) m = fmaxf(m, __shfl_xor_sync(0xffffffffu, m, off));
    float s = expf(a0 - m) + (has1 ? expf(a1 - m) : 0.f);
#pragma unroll
    for (int off = 16; off; off >>= 1) s += __shfl_xor_sync(0xffffffffu, s, off);
    float lse = m + logf(s);
    out[(size_t)r * NCLASS + j0] = a0 - lse;
    if (has1) out[(size_t)r * NCLASS + j1] = a1 - lse;
}

// ---------------- launch ----------------
extern "C" void kernel_launch(void* const* d_in, const int* in_sizes, int n_in,
                              void* d_out, int out_size) {
    const float* x = (const float*)d_in[0];
    const void* ei = (const void*)d_in[1];
    const float* W1 = (const float*)d_in[2];
    const float* b1 = (const float*)d_in[3];
    const float* convW = (const float*)d_in[4];
    const float* W2 = (const float*)d_in[5];
    const float* b2 = (const float*)d_in[6];
    float* out = (float*)d_out;

    const int TB = 256;
    const int nblkN = (NN + TB - 1) / TB;
    const int nblkE = (EE + TB - 1) / TB;
    const int nscan = (NN + 1023) / 1024;      // 98
    const int nrowblk = (NN + 63) / 64;        // 1563

    // detect edge_index element width (int32 vs int64), then build CSR
    detect_kernel<<<1, 32>>>((const unsigned int*)ei);
    zero_cnt_kernel<<<nblkN, TB>>>();
    count_kernel<<<nblkE, TB>>>(ei);
    scan1_kernel<<<nscan, TB>>>();
    scan2_kernel<<<1, 32>>>(nscan);
    scan3_kernel<<<nblkN, TB>>>();
    scatter_kernel<<<nblkE, TB>>>(ei);

    // x0 (fp32 residual copy + fp16 seed in g_hA)
    x0_kernel<<<nrowblk, TB>>>(x, W1, b1);

    // 64 fused layers (ping-pong: A -> B -> A -> ...)
    int sel_in = 1;
    for (int l = 0; l < NLAYER; l++) {
        float beta = logf(THETA / (float)(l + 1) + 1.0f);
        int sel_out = 3 - sel_in;
        layer_kernel<<<nrowblk, TB>>>(convW + (size_t)l * HID * HID, beta, sel_in, sel_out);
        sel_in = sel_out;
    }

    // logits + log_softmax (l=63 wrote buffer A -> sel_in==1)
    out_kernel<<<(NN + 7) / 8, TB>>>(sel_in, W2, b2, out);
}

// round 7
// speedup vs baseline: 1.4151x; 1.0876x over previous
#include <cuda_runtime.h>
#include <cuda_fp16.h>
#include <math.h>

// ---------------- problem constants (fixed-shape problem) ----------------
#define NN 100000
#define EE 3200000
#define F_IN 128
#define HID 64
#define NLAYER 64
#define NCLASS 47
#define ALPHA 0.1f
#define THETA 0.5f

// ---------------- scratch (static device globals; no allocation) ---------
__device__ __align__(16) float  g_x0[NN * HID];   // relu(x@W1+b1), fp32 residual
__device__ __align__(16) __half g_hA[NN * HID];   // ping (fp16 feature rows)
__device__ __align__(16) __half g_hB[NN * HID];   // pong
__device__ __align__(16) int2   g_colw[EE];       // packed {col, weight bits}
__device__ int   g_rowptr[NN + 1];
__device__ int   g_cnt[NN];
__device__ int   g_cursor[NN];
__device__ float g_dinv[NN];
__device__ int   g_bsum[128];
__device__ int   g_is64;        // 1 if edge_index buffer is int64, 0 if int32

__device__ __forceinline__ const __half* pick_half(int s) {
    return (s == 1) ? g_hA : g_hB;
}
__device__ __forceinline__ __half* pick_half_mut(int s) {
    return (s == 1) ? g_hA : g_hB;
}

// packed f32x2 fma: d = a*b + d  (each 64-bit reg = two packed floats)
__device__ __forceinline__ void fma2(unsigned long long& d,
                                     unsigned long long a,
                                     unsigned long long b) {
    asm("fma.rn.f32x2 %0, %1, %2, %0;" : "+l"(d) : "l"(a), "l"(b));
}

// ---------------- edge dtype detection ----------------
__global__ void detect_kernel(const unsigned int* __restrict__ p) {
    if (threadIdx.x == 0 && blockIdx.x == 0) {
        int all0 = 1;
        for (int i = 0; i < 64; i++) {
            if (p[2 * i + 1] != 0u) { all0 = 0; break; }
        }
        g_is64 = all0;
    }
}

__device__ __forceinline__ int edge_at(const void* eiv, size_t idx, int is64) {
    if (is64) return (int)((const long long*)eiv)[idx];
    return ((const int*)eiv)[idx];
}

// ---------------- CSR construction ----------------
__global__ void zero_cnt_kernel() {
    int i = blockIdx.x * blockDim.x + threadIdx.x;
    if (i < NN) g_cnt[i] = 0;
}

__global__ void count_kernel(const void* __restrict__ eiv) {
    int i = blockIdx.x * blockDim.x + threadIdx.x;
    int is64 = g_is64;
    if (i < EE) {
        int dst = edge_at(eiv, (size_t)EE + i, is64);
        atomicAdd(&g_cnt[dst], 1);
    }
}

// block-level exclusive scan over 1024 elements (256 thr x 4)
__global__ void scan1_kernel() {
    __shared__ int sh[256];
    int t = threadIdx.x, b = blockIdx.x;
    int base = b * 1024 + t * 4;
    int v0 = (base + 0 < NN) ? g_cnt[base + 0] : 0;
    int v1 = (base + 1 < NN) ? g_cnt[base + 1] : 0;
    int v2 = (base + 2 < NN) ? g_cnt[base + 2] : 0;
    int v3 = (base + 3 < NN) ? g_cnt[base + 3] : 0;
    int s0 = v0, s1 = s0 + v1, s2 = s1 + v2, s3 = s2 + v3;
    sh[t] = s3;
    __syncthreads();
    for (int off = 1; off < 256; off <<= 1) {
        int v = (t >= off) ? sh[t - off] : 0;
        __syncthreads();
        sh[t] += v;
        __syncthreads();
    }
    int excl = sh[t] - s3;
    if (base + 0 < NN) g_rowptr[base + 0] = excl;
    if (base + 1 < NN) g_rowptr[base + 1] = excl + s0;
    if (base + 2 < NN) g_rowptr[base + 2] = excl + s1;
    if (base + 3 < NN) g_rowptr[base + 3] = excl + s2;
    if (t == 255) g_bsum[b] = sh[255];
}

__global__ void scan2_kernel(int nblk) {
    if (threadIdx.x == 0 && blockIdx.x == 0) {
        int run = 0;
        for (int b = 0; b < nblk; b++) {
            int v = g_bsum[b];
            g_bsum[b] = run;
            run += v;
        }
        g_rowptr[NN] = run;  // == EE
    }
}

__global__ void scan3_kernel() {
    int i = blockIdx.x * blockDim.x + threadIdx.x;
    if (i < NN) {
        int rp = g_rowptr[i] + g_bsum[i >> 10];
        g_rowptr[i] = rp;
        g_cursor[i] = rp;
        g_dinv[i] = rsqrtf((float)(g_cnt[i] + 1));  // +1 self loop
    }
}

// scatter edges AND bake layer-invariant weight dinv[dst]*dinv[src] into 8B slot
__global__ void scatter_kernel(const void* __restrict__ eiv) {
    int i = blockIdx.x * blockDim.x + threadIdx.x;
    int is64 = g_is64;
    if (i < EE) {
        int src = edge_at(eiv, (size_t)i, is64);
        int dst = edge_at(eiv, (size_t)EE + i, is64);
        int pos = atomicAdd(&g_cursor[dst], 1);
        float w = g_dinv[dst] * g_dinv[src];
        g_colw[pos] = make_int2(src, __float_as_int(w));
    }
}

// ---------------- x0 = relu(x @ W1 + b1); also seed fp16 copy in g_hA ----
__global__ void __launch_bounds__(256) x0_kernel(const float* __restrict__ x,
                                                 const float* __restrict__ W1,
                                                 const float* __restrict__ b1) {
    __shared__ __align__(16) float Ws[F_IN * HID];  // 32KB
    int tid = threadIdx.x;
    const float4* W4 = (const float4*)W1;
    float4* Ws4 = (float4*)Ws;
#pragma unroll
    for (int i = tid; i < (F_IN * HID) / 4; i += 256) Ws4[i] = W4[i];
    __syncthreads();

    int base = blockIdx.x * 64;
    int w = tid >> 5, lane = tid & 31;
    float bx = b1[2 * lane], by = b1[2 * lane + 1];
#pragma unroll 1
    for (int i = 0; i < 8; i++) {
        int r = base + w * 8 + i;
        if (r >= NN) continue;
        float ax = bx, ay = by;
        const float4* xr = (const float4*)(x + (size_t)r * F_IN);
#pragma unroll 8
        for (int kk = 0; kk < F_IN / 4; kk++) {
            float4 xv = xr[kk];
            int k = kk * 4;
            float2 w0 = ((const float2*)(Ws + (k + 0) * HID))[lane];
            float2 w1 = ((const float2*)(Ws + (k + 1) * HID))[lane];
            float2 w2 = ((const float2*)(Ws + (k + 2) * HID))[lane];
            float2 w3 = ((const float2*)(Ws + (k + 3) * HID))[lane];
            ax += xv.x * w0.x; ay += xv.x * w0.y;
            ax += xv.y * w1.x; ay += xv.y * w1.y;
            ax += xv.z * w2.x; ay += xv.z * w2.y;
            ax += xv.w * w3.x; ay += xv.w * w3.y;
        }
        float vx = fmaxf(ax, 0.f), vy = fmaxf(ay, 0.f);
        ((float2*)(g_x0 + (size_t)r * HID))[lane] = make_float2(vx, vy);
        ((__half2*)(g_hA + (size_t)r * HID))[lane] = __floats2half2_rn(vx, vy);
    }
}

// ---------------- fused layer: SPMM(fp16 gather) + mix + (1-b)s + b*(s@W) + relu
__global__ void __launch_bounds__(256) layer_kernel(const float* __restrict__ Wl,
                                                    float beta, int sel_in, int sel_out) {
    __shared__ __align__(16) float Ws[HID * HID];    // 16KB
    __shared__ __align__(16) float ss[64 * 65];      // 16.6KB, pitch 65
    const __half* __restrict__ hin = pick_half(sel_in);
    __half* __restrict__ hout = pick_half_mut(sel_out);

    int tid = threadIdx.x;
    {   // stage Wl
        const float4* W4 = (const float4*)Wl;
        float4* Ws4 = (float4*)Ws;
#pragma unroll
        for (int i = tid; i < (HID * HID) / 4; i += 256) Ws4[i] = W4[i];
    }

    int base = blockIdx.x * 64;
    int w = tid >> 5, lane = tid & 31;
    int g = lane >> 4;          // edge parity group (0/1)
    int t = lane & 15;          // feature slot: features 4t..4t+3
    const unsigned FULL = 0xffffffffu;

    // -------- phase 1: warp-per-row gather, 2 edges per LDG.64 --------
    // Lanes 0-15 fetch edge 2p, lanes 16-31 fetch edge 2p+1; each lane loads
    // uint2 = 4 fp16 features. Per 32-edge chunk: 16 warp LDGs (vs 32).
    // Halves combined at row end with one shfl_xor(16).
#pragma unroll 1
    for (int i = 0; i < 8; i++) {
        int rl = w * 8 + i;
        int r = base + rl;
        if (r < NN) {
            float dr = g_dinv[r];
            float a0 = 0.f, a1 = 0.f, a2 = 0.f, a3 = 0.f;
            int e = g_rowptr[r];
            const int e1 = g_rowptr[r + 1];
#pragma unroll 1
            while (e < e1) {
                int rem = e1 - e;
                int2 cw = make_int2(0, 0);
                if (lane < rem) cw = g_colw[e + lane];
                int np = rem < 32 ? rem : 32;
                int npr = (((np + 1) >> 1) + 3) & ~3;   // pairs, rounded to 4

                uint2 ha[4];
#pragma unroll
                for (int q = 0; q < 4; q++) {
                    int c = __shfl_sync(FULL, cw.x, 2 * q + g);
                    ha[q] = ((const uint2*)(hin + (size_t)c * HID))[t];
                }
                int pprev = 0;
#pragma unroll 1
                for (int p0 = 4; p0 < npr; p0 += 4) {
                    uint2 hb[4];
#pragma unroll
                    for (int q = 0; q < 4; q++) {
                        int c = __shfl_sync(FULL, cw.x, 2 * (p0 + q) + g);
                        hb[q] = ((const uint2*)(hin + (size_t)c * HID))[t];
                    }
#pragma unroll
                    for (int q = 0; q < 4; q++) {
                        float wq = __int_as_float(__shfl_sync(FULL, cw.y, 2 * (pprev + q) + g));
                        float2 f0 = __half22float2(*(__half2*)&ha[q].x);
                        float2 f1 = __half22float2(*(__half2*)&ha[q].y);
                        a0 += wq * f0.x; a1 += wq * f0.y;
                        a2 += wq * f1.x; a3 += wq * f1.y;
                    }
#pragma unroll
                    for (int q = 0; q < 4; q++) ha[q] = hb[q];
                    pprev = p0;
                }
#pragma unroll
                for (int q = 0; q < 4; q++) {
                    float wq = __int_as_float(__shfl_sync(FULL, cw.y, 2 * (pprev + q) + g));
                    float2 f0 = __half22float2(*(__half2*)&ha[q].x);
                    float2 f1 = __half22float2(*(__half2*)&ha[q].y);
                    a0 += wq * f0.x; a1 += wq * f0.y;
                    a2 += wq * f1.x; a3 += wq * f1.y;
                }
                e += 32;
            }
            // combine halves (each lane then holds the full sum for feats 4t..4t+3)
            a0 += __shfl_xor_sync(FULL, a0, 16);
            a1 += __shfl_xor_sync(FULL, a1, 16);
            a2 += __shfl_xor_sync(FULL, a2, 16);
            a3 += __shfl_xor_sync(FULL, a3, 16);
            // self-loop (added once, post-combine)
            float ws = dr * dr;
            uint2 hs = ((const uint2*)(hin + (size_t)r * HID))[t];
            float2 s0f = __half22float2(*(__half2*)&hs.x);
            float2 s1f = __half22float2(*(__half2*)&hs.y);
            a0 += ws * s0f.x; a1 += ws * s0f.y;
            a2 += ws * s1f.x; a3 += ws * s1f.y;
            // initial-residual mix
            float4 x0v = ((const float4*)(g_x0 + (size_t)r * HID))[t];
            if (lane < 16) {
                int bsh = rl * 65 + 4 * t;
                ss[bsh + 0] = (1.f - ALPHA) * a0 + ALPHA * x0v.x;
                ss[bsh + 1] = (1.f - ALPHA) * a1 + ALPHA * x0v.y;
                ss[bsh + 2] = (1.f - ALPHA) * a2 + ALPHA * x0v.z;
                ss[bsh + 3] = (1.f - ALPHA) * a3 + ALPHA * x0v.w;
            }
        }
    }
    __syncthreads();

    // -------- phase 2: 64x64 @ 64x64 GEMM from shared, packed f32x2 FMA ----
    int rl = tid & 63;
    int gq = tid >> 6;          // 4 groups of 16 columns
    int cbase = gq * 16;
    unsigned long long acc[8];
#pragma unroll
    for (int i = 0; i < 8; i++) acc[i] = 0ull;
#pragma unroll 8
    for (int k = 0; k < HID; k++) {
        float sk = ss[rl * 65 + k];
        unsigned long long skk;
        asm("mov.b64 %0, {%1, %2};" : "=l"(skk) : "f"(sk), "f"(sk));
        const ulonglong2* wp = (const ulonglong2*)(Ws + k * HID + cbase);  // warp-uniform
        ulonglong2 p0 = wp[0], p1 = wp[1], p2 = wp[2], p3 = wp[3];
        fma2(acc[0], p0.x, skk); fma2(acc[1], p0.y, skk);
        fma2(acc[2], p1.x, skk); fma2(acc[3], p1.y, skk);
        fma2(acc[4], p2.x, skk); fma2(acc[5], p2.y, skk);
        fma2(acc[6], p3.x, skk); fma2(acc[7], p3.y, skk);
    }
    int r = base + rl;
    if (r < NN) {
        float ob = 1.f - beta;
        unsigned int u[8];
#pragma unroll
        for (int q = 0; q < 8; q++) {
            float lo, hi;
            asm("mov.b64 {%0, %1}, %2;" : "=f"(lo), "=f"(hi) : "l"(acc[q]));
            float v0 = fmaxf(ob * ss[rl * 65 + cbase + 2 * q + 0] + beta * lo, 0.f);
            float v1 = fmaxf(ob * ss[rl * 65 + cbase + 2 * q + 1] + beta * hi, 0.f);
            __half2 h2 = __floats2half2_rn(v0, v1);
            u[q] = *(unsigned int*)&h2;
        }
        uint4* dst = (uint4*)(hout + (size_t)r * HID + cbase);  // 32B-aligned
        dst[0] = make_uint4(u[0], u[1], u[2], u[3]);
        dst[1] = make_uint4(u[4], u[5], u[6], u[7]);
    }
}

// ---------------- logits + log_softmax ----------------
__global__ void __launch_bounds__(256) out_kernel(int sel_in,
                                                  const float* __restrict__ W2,
                                                  const float* __restrict__ b2,
                                                  float* __restrict__ out) {
    __shared__ float W2s[HID * NCLASS];
    __shared__ float b2s[NCLASS];
    __shared__ float hrow[8][HID];
    const __half* __restrict__ hin = pick_half(sel_in);

    int tid = threadIdx.x;
    for (int i = tid; i < HID * NCLASS; i += 256) W2s[i] = W2[i];
    if (tid < NCLASS) b2s[tid] = b2[tid];
    __syncthreads();

    int w = tid >> 5, lane = tid & 31;
    int r = blockIdx.x * 8 + w;
    if (r < NN) {
        hrow[w][lane] = __half2float(hin[(size_t)r * HID + lane]);
        hrow[w][lane + 32] = __half2float(hin[(size_t)r * HID + lane + 32]);
    }
    __syncwarp();
    if (r >= NN) return;

    int j0 = lane, j1 = lane + 32;
    bool has1 = (j1 < NCLASS);
    float a0 = b2s[j0];
    float a1 = has1 ? b2s[j1] : 0.f;
#pragma unroll 4
    for (int k = 0; k < HID; k++) {
        float hv = hrow[w][k];
        a0 += hv * W2s[k * NCLASS + j0];
        if (has1) a1 += hv * W2s[k * NCLASS + j1];
    }
    float m = a0;
    if (has1) m = fmaxf(m, a1);
#pragma unroll
    for (int off = 16; off; off >>= 1) m = fmaxf(m, __shfl_xor_sync(0xffffffffu, m, off));
    float s = expf(a0 - m) + (has1 ? expf(a1 - m) : 0.f);
#pragma unroll
    for (int off = 16; off; off >>= 1) s += __shfl_xor_sync(0xffffffffu, s, off);
    float lse = m + logf(s);
    out[(size_t)r * NCLASS + j0] = a0 - lse;
    if (has1) out[(size_t)r * NCLASS + j1] = a1 - lse;
}

// ---------------- launch ----------------
extern "C" void kernel_launch(void* const* d_in, const int* in_sizes, int n_in,
                              void* d_out, int out_size) {
    const float* x = (const float*)d_in[0];
    const void* ei = (const void*)d_in[1];
    const float* W1 = (const float*)d_in[2];
    const float* b1 = (const float*)d_in[3];
    const float* convW = (const float*)d_in[4];
    const float* W2 = (const float*)d_in[5];
    const float* b2 = (const float*)d_in[6];
    float* out = (float*)d_out;

    const int TB = 256;
    const int nblkN = (NN + TB - 1) / TB;
    const int nblkE = (EE + TB - 1) / TB;
    const int nscan = (NN + 1023) / 1024;      // 98
    const int nrowblk = (NN + 63) / 64;        // 1563

    // detect edge_index element width (int32 vs int64), then build CSR
    detect_kernel<<<1, 32>>>((const unsigned int*)ei);
    zero_cnt_kernel<<<nblkN, TB>>>();
    count_kernel<<<nblkE, TB>>>(ei);
    scan1_kernel<<<nscan, TB>>>();
    scan2_kernel<<<1, 32>>>(nscan);
    scan3_kernel<<<nblkN, TB>>>();
    scatter_kernel<<<nblkE, TB>>>(ei);

    // x0 (fp32 residual copy + fp16 seed in g_hA)
    x0_kernel<<<nrowblk, TB>>>(x, W1, b1);

    // 64 fused layers (ping-pong: A -> B -> A -> ...)
    int sel_in = 1;
    for (int l = 0; l < NLAYER; l++) {
        float beta = logf(THETA / (float)(l + 1) + 1.0f);
        int sel_out = 3 - sel_in;
        layer_kernel<<<nrowblk, TB>>>(convW + (size_t)l * HID * HID, beta, sel_in, sel_out);
        sel_in = sel_out;
    }

    // logits + log_softmax (l=63 wrote buffer A -> sel_in==1)
    out_kernel<<<(NN + 7) / 8, TB>>>(sel_in, W2, b2, out);
}

// round 8
// speedup vs baseline: 1.6325x; 1.1536x over previous
#include <cuda_runtime.h>
#include <cuda_fp16.h>
#include <math.h>

// ---------------- problem constants (fixed-shape problem) ----------------
#define NN 100000
#define EE 3200000
#define F_IN 128
#define HID 64
#define NLAYER 64
#define NCLASS 47
#define ALPHA 0.1f
#define THETA 0.5f

// ---------------- scratch (static device globals; no allocation) ---------
// Feature buffers hold PRE-SCALED rows:  hhat = dinv[r] * h[r]  (fp16).
// Row NN is a phantom all-zero row used to pad edge-chunk tails.
__device__ __align__(16) float  g_x0[NN * HID];          // relu(x@W1+b1), fp32
__device__ __align__(16) __half g_hA[(NN + 1) * HID];    // ping
__device__ __align__(16) __half g_hB[(NN + 1) * HID];    // pong
__device__ int   g_col[EE];          // CSR column indices
__device__ int   g_rowptr[NN + 1];
__device__ int   g_cnt[NN];          // zero at load; self-cleaned each run
__device__ int   g_cursor[NN];
__device__ float g_dinv[NN];         // 1/sqrt(deg+1)
__device__ float g_rdinv[NN];        // sqrt(deg+1)
__device__ int   g_bsum[128];
__device__ int   g_is64;

__device__ __forceinline__ const __half* pick_half(int s) {
    return (s == 1) ? g_hA : g_hB;
}
__device__ __forceinline__ __half* pick_half_mut(int s) {
    return (s == 1) ? g_hA : g_hB;
}

// packed f32x2 fma: d = a*b + d
__device__ __forceinline__ void fma2(unsigned long long& d,
                                     unsigned long long a,
                                     unsigned long long b) {
    asm("fma.rn.f32x2 %0, %1, %2, %0;" : "+l"(d) : "l"(a), "l"(b));
}

__device__ __forceinline__ int edge_at(const void* eiv, size_t idx, int is64) {
    if (is64) return (int)((const long long*)eiv)[idx];
    return ((const int*)eiv)[idx];
}

// ---------------- x0 = relu(x @ W1 + b1)  (+ inline edge-dtype detect) ----
__global__ void __launch_bounds__(256) x0_kernel(const float* __restrict__ x,
                                                 const float* __restrict__ W1,
                                                 const float* __restrict__ b1,
                                                 const unsigned int* __restrict__ eip) {
    if (blockIdx.x == 0 && threadIdx.x == 0) {
        // int64 little-endian with values < 2^32 -> odd words all zero
        int all0 = 1;
        for (int i = 0; i < 64; i++) {
            if (eip[2 * i + 1] != 0u) { all0 = 0; break; }
        }
        g_is64 = all0;
    }

    __shared__ __align__(16) float Ws[F_IN * HID];  // 32KB
    int tid = threadIdx.x;
    const float4* W4 = (const float4*)W1;
    float4* Ws4 = (float4*)Ws;
#pragma unroll
    for (int i = tid; i < (F_IN * HID) / 4; i += 256) Ws4[i] = W4[i];
    __syncthreads();

    int base = blockIdx.x * 64;
    int w = tid >> 5, lane = tid & 31;
    float bx = b1[2 * lane], by = b1[2 * lane + 1];
#pragma unroll 1
    for (int i = 0; i < 8; i++) {
        int r = base + w * 8 + i;
        if (r >= NN) continue;
        float ax = bx, ay = by;
        const float4* xr = (const float4*)(x + (size_t)r * F_IN);
#pragma unroll 8
        for (int kk = 0; kk < F_IN / 4; kk++) {
            float4 xv = xr[kk];
            int k = kk * 4;
            float2 w0 = ((const float2*)(Ws + (k + 0) * HID))[lane];
            float2 w1 = ((const float2*)(Ws + (k + 1) * HID))[lane];
            float2 w2 = ((const float2*)(Ws + (k + 2) * HID))[lane];
            float2 w3 = ((const float2*)(Ws + (k + 3) * HID))[lane];
            ax += xv.x * w0.x; ay += xv.x * w0.y;
            ax += xv.y * w1.x; ay += xv.y * w1.y;
            ax += xv.z * w2.x; ay += xv.z * w2.y;
            ax += xv.w * w3.x; ay += xv.w * w3.y;
        }
        float vx = fmaxf(ax, 0.f), vy = fmaxf(ay, 0.f);
        ((float2*)(g_x0 + (size_t)r * HID))[lane] = make_float2(vx, vy);
    }
}

// ---------------- CSR: count ----------------
__global__ void count_kernel(const void* __restrict__ eiv) {
    int i = blockIdx.x * blockDim.x + threadIdx.x;
    int is64 = g_is64;
    if (i < EE) {
        int dst = edge_at(eiv, (size_t)EE + i, is64);
        atomicAdd(&g_cnt[dst], 1);
    }
}

// ---------------- CSR: block-local exclusive scan (1024 per block) -------
__global__ void scan1_kernel() {
    __shared__ int sh[256];
    int t = threadIdx.x, b = blockIdx.x;
    int base = b * 1024 + t * 4;
    int v0 = (base + 0 < NN) ? g_cnt[base + 0] : 0;
    int v1 = (base + 1 < NN) ? g_cnt[base + 1] : 0;
    int v2 = (base + 2 < NN) ? g_cnt[base + 2] : 0;
    int v3 = (base + 3 < NN) ? g_cnt[base + 3] : 0;
    int s0 = v0, s1 = s0 + v1, s2 = s1 + v2, s3 = s2 + v3;
    sh[t] = s3;
    __syncthreads();
    for (int off = 1; off < 256; off <<= 1) {
        int v = (t >= off) ? sh[t - off] : 0;
        __syncthreads();
        sh[t] += v;
        __syncthreads();
    }
    int excl = sh[t] - s3;
    if (base + 0 < NN) g_rowptr[base + 0] = excl;
    if (base + 1 < NN) g_rowptr[base + 1] = excl + s0;
    if (base + 2 < NN) g_rowptr[base + 2] = excl + s1;
    if (base + 3 < NN) g_rowptr[base + 3] = excl + s2;
    if (t == 255) g_bsum[b] = sh[255];
}

// ---------------- CSR: finalize (inline bsum prefix) + dinv + seed hA ----
__global__ void __launch_bounds__(256) scan3_kernel() {
    __shared__ int pre_sh;
    int t = threadIdx.x, b = blockIdx.x;
    if (t == 0) {
        int nb = b >> 2;           // 1024-node block index for this 256-block
        int run = 0;
        for (int j = 0; j < nb; j++) run += g_bsum[j];
        pre_sh = run;
    }
    __syncthreads();
    int i = b * 256 + t;
    if (i < NN) {
        int rp = g_rowptr[i] + pre_sh;
        g_rowptr[i] = rp;
        g_cursor[i] = rp;
        int deg = g_cnt[i] + 1;    // +1 self loop
        float di = rsqrtf((float)deg);
        g_dinv[i] = di;
        g_rdinv[i] = sqrtf((float)deg);
        g_cnt[i] = 0;              // self-clean for next graph replay
        // seed hA with hhat0 = dinv * x0 (fp16)
        const float2* xr = (const float2*)(g_x0 + (size_t)i * HID);
        __half2* hw = (__half2*)(g_hA + (size_t)i * HID);
#pragma unroll
        for (int k = 0; k < 32; k++) {
            float2 v = xr[k];
            hw[k] = __floats2half2_rn(di * v.x, di * v.y);
        }
    }
    if (i == 0) g_rowptr[NN] = EE;
    if (b == 0 && t < 64) {        // phantom row NN = 0 in both buffers
        g_hA[(size_t)NN * HID + t] = __float2half(0.f);
        g_hB[(size_t)NN * HID + t] = __float2half(0.f);
    }
}

// ---------------- CSR: scatter ----------------
__global__ void scatter_kernel(const void* __restrict__ eiv) {
    int i = blockIdx.x * blockDim.x + threadIdx.x;
    int is64 = g_is64;
    if (i < EE) {
        int src = edge_at(eiv, (size_t)i, is64);
        int dst = edge_at(eiv, (size_t)EE + i, is64);
        int pos = atomicAdd(&g_cursor[dst], 1);
        g_col[pos] = src;
    }
}

// ---------------- fused layer --------------------------------------------
// phase 1: p[r] = dinv[r] * (sum_edges hhat[c] + hhat[r])   (pure sum!)
//          s    = (1-a)*p + a*x0
// phase 2: h = relu((1-b)s + b*(s@W));  store hhat = dinv[r]*h as fp16
__global__ void __launch_bounds__(256) layer_kernel(const float* __restrict__ Wl,
                                                    float beta, int sel_in, int sel_out) {
    __shared__ __align__(16) float Ws[HID * HID];    // 16KB
    __shared__ __align__(16) float ss[64 * 65];      // 16.6KB, pitch 65
    const __half* __restrict__ hin = pick_half(sel_in);
    __half* __restrict__ hout = pick_half_mut(sel_out);

    int tid = threadIdx.x;
    {   // stage Wl
        const float4* W4 = (const float4*)Wl;
        float4* Ws4 = (float4*)Ws;
#pragma unroll
        for (int i = tid; i < (HID * HID) / 4; i += 256) Ws4[i] = W4[i];
    }

    int base = blockIdx.x * 64;
    int w = tid >> 5, lane = tid & 31;
    int g = lane >> 4;          // edge parity group (0/1)
    int t = lane & 15;          // feature slot: features 4t..4t+3
    const unsigned FULL = 0xffffffffu;

    // -------- phase 1: warp-per-row unweighted gather --------
    // 32 cols loaded coalesced per chunk; processed in 8-edge subchunks
    // (4 pairs each, 2 edges per LDG.64), software-pipelined. Tail lanes
    // use phantom row NN (all zeros) so the loop body is branch-free.
#pragma unroll 1
    for (int i = 0; i < 8; i++) {
        int rl = w * 8 + i;
        int r = base + rl;
        if (r < NN) {
            float a0 = 0.f, a1 = 0.f, a2 = 0.f, a3 = 0.f;
            int e = g_rowptr[r];
            const int e1 = g_rowptr[r + 1];
#pragma unroll 1
            while (e < e1) {
                int rem = e1 - e;
                int cw = (lane < rem) ? g_col[e + lane] : NN;
                int np = rem < 32 ? rem : 32;
                int nsub = (np + 7) >> 3;

                uint2 ha[4];
#pragma unroll
                for (int q = 0; q < 4; q++) {
                    int idx = 2 * q + g;
                    int c = __shfl_sync(FULL, cw, idx);
                    if (idx >= np) c = NN;
                    ha[q] = ((const uint2*)(hin + (size_t)c * HID))[t];
                }
#pragma unroll 1
                for (int s = 1; s < nsub; s++) {
                    uint2 hb[4];
#pragma unroll
                    for (int q = 0; q < 4; q++) {
                        int idx = 8 * s + 2 * q + g;
                        int c = __shfl_sync(FULL, cw, idx);
                        if (idx >= np) c = NN;
                        hb[q] = ((const uint2*)(hin + (size_t)c * HID))[t];
                    }
#pragma unroll
                    for (int q = 0; q < 4; q++) {
                        float2 f0 = __half22float2(*(__half2*)&ha[q].x);
                        float2 f1 = __half22float2(*(__half2*)&ha[q].y);
                        a0 += f0.x; a1 += f0.y; a2 += f1.x; a3 += f1.y;
                        ha[q] = hb[q];
                    }
                }
#pragma unroll
                for (int q = 0; q < 4; q++) {
                    float2 f0 = __half22float2(*(__half2*)&ha[q].x);
                    float2 f1 = __half22float2(*(__half2*)&ha[q].y);
                    a0 += f0.x; a1 += f0.y; a2 += f1.x; a3 += f1.y;
                }
                e += 32;
            }
            // combine the two 16-lane halves
            a0 += __shfl_xor_sync(FULL, a0, 16);
            a1 += __shfl_xor_sync(FULL, a1, 16);
            a2 += __shfl_xor_sync(FULL, a2, 16);
            a3 += __shfl_xor_sync(FULL, a3, 16);
            // self loop: + hhat[r], then scale by dinv[r]
            uint2 hs = ((const uint2*)(hin + (size_t)r * HID))[t];
            float2 s0f = __half22float2(*(__half2*)&hs.x);
            float2 s1f = __half22float2(*(__half2*)&hs.y);
            a0 += s0f.x; a1 += s0f.y; a2 += s1f.x; a3 += s1f.y;
            float dr = g_dinv[r];
            float4 x0v = ((const float4*)(g_x0 + (size_t)r * HID))[t];
            if (lane < 16) {
                int bsh = rl * 65 + 4 * t;
                ss[bsh + 0] = (1.f - ALPHA) * (dr * a0) + ALPHA * x0v.x;
                ss[bsh + 1] = (1.f - ALPHA) * (dr * a1) + ALPHA * x0v.y;
                ss[bsh + 2] = (1.f - ALPHA) * (dr * a2) + ALPHA * x0v.z;
                ss[bsh + 3] = (1.f - ALPHA) * (dr * a3) + ALPHA * x0v.w;
            }
        }
    }
    __syncthreads();

    // -------- phase 2: 64x64 @ 64x64 GEMM from shared, packed f32x2 FMA ----
    int rl = tid & 63;
    int gq = tid >> 6;          // 4 groups of 16 columns
    int cbase = gq * 16;
    unsigned long long acc[8];
#pragma unroll
    for (int i = 0; i < 8; i++) acc[i] = 0ull;
#pragma unroll 8
    for (int k = 0; k < HID; k++) {
        float sk = ss[rl * 65 + k];
        unsigned long long skk;
        asm("mov.b64 %0, {%1, %2};" : "=l"(skk) : "f"(sk), "f"(sk));
        const ulonglong2* wp = (const ulonglong2*)(Ws + k * HID + cbase);  // warp-uniform
        ulonglong2 p0 = wp[0], p1 = wp[1], p2 = wp[2], p3 = wp[3];
        fma2(acc[0], p0.x, skk); fma2(acc[1], p0.y, skk);
        fma2(acc[2], p1.x, skk); fma2(acc[3], p1.y, skk);
        fma2(acc[4], p2.x, skk); fma2(acc[5], p2.y, skk);
        fma2(acc[6], p3.x, skk); fma2(acc[7], p3.y, skk);
    }
    int r = base + rl;
    if (r < NN) {
        float ob = 1.f - beta;
        float di = g_dinv[r];
        unsigned int u[8];
#pragma unroll
        for (int q = 0; q < 8; q++) {
            float lo, hi;
            asm("mov.b64 {%0, %1}, %2;" : "=f"(lo), "=f"(hi) : "l"(acc[q]));
            float v0 = fmaxf(ob * ss[rl * 65 + cbase + 2 * q + 0] + beta * lo, 0.f);
            float v1 = fmaxf(ob * ss[rl * 65 + cbase + 2 * q + 1] + beta * hi, 0.f);
            __half2 h2 = __floats2half2_rn(di * v0, di * v1);
            u[q] = *(unsigned int*)&h2;
        }
        uint4* dst = (uint4*)(hout + (size_t)r * HID + cbase);  // 32B-aligned
        dst[0] = make_uint4(u[0], u[1], u[2], u[3]);
        dst[1] = make_uint4(u[4], u[5], u[6], u[7]);
    }
}

// ---------------- logits + log_softmax ----------------
__global__ void __launch_bounds__(256) out_kernel(int sel_in,
                                                  const float* __restrict__ W2,
                                                  const float* __restrict__ b2,
                                                  float* __restrict__ out) {
    __shared__ float W2s[HID * NCLASS];
    __shared__ float b2s[NCLASS];
    __shared__ float hrow[8][HID];
    const __half* __restrict__ hin = pick_half(sel_in);

    int tid = threadIdx.x;
    for (int i = tid; i < HID * NCLASS; i += 256) W2s[i] = W2[i];
    if (tid < NCLASS) b2s[tid] = b2[tid];
    __syncthreads();

    int w = tid >> 5, lane = tid & 31;
    int r = blockIdx.x * 8 + w;
    if (r < NN) {
        float rdi = g_rdinv[r];   // undo the dinv pre-scaling
        hrow[w][lane] = rdi * __half2float(hin[(size_t)r * HID + lane]);
        hrow[w][lane + 32] = rdi * __half2float(hin[(size_t)r * HID + lane + 32]);
    }
    __syncwarp();
    if (r >= NN) return;

    int j0 = lane, j1 = lane + 32;
    bool has1 = (j1 < NCLASS);
    float a0 = b2s[j0];
    float a1 = has1 ? b2s[j1] : 0.f;
#pragma unroll 4
    for (int k = 0; k < HID; k++) {
        float hv = hrow[w][k];
        a0 += hv * W2s[k * NCLASS + j0];
        if (has1) a1 += hv * W2s[k * NCLASS + j1];
    }
    float m = a0;
    if (has1) m = fmaxf(m, a1);
#pragma unroll
    for (int off = 16; off; off >>= 1) m = fmaxf(m, __shfl_xor_sync(0xffffffffu, m, off));
    float s = expf(a0 - m) + (has1 ? expf(a1 - m) : 0.f);
#pragma unroll
    for (int off = 16; off; off >>= 1) s += __shfl_xor_sync(0xffffffffu, s, off);
    float lse = m + logf(s);
    out[(size_t)r * NCLASS + j0] = a0 - lse;
    if (has1) out[(size_t)r * NCLASS + j1] = a1 - lse;
}

// ---------------- launch ----------------
extern "C" void kernel_launch(void* const* d_in, const int* in_sizes, int n_in,
                              void* d_out, int out_size) {
    const float* x = (const float*)d_in[0];
    const void* ei = (const void*)d_in[1];
    const float* W1 = (const float*)d_in[2];
    const float* b1 = (const float*)d_in[3];
    const float* convW = (const float*)d_in[4];
    const float* W2 = (const float*)d_in[5];
    const float* b2 = (const float*)d_in[6];
    float* out = (float*)d_out;

    const int TB = 256;
    const int nblkN = (NN + TB - 1) / TB;      // 391
    const int nblkE = (EE + TB - 1) / TB;
    const int nscan = (NN + 1023) / 1024;      // 98
    const int nrowblk = (NN + 63) / 64;        // 1563

    // 5 preamble launches (g_cnt is zero at load and self-cleaned by scan3)
    x0_kernel<<<nrowblk, TB>>>(x, W1, b1, (const unsigned int*)ei);  // + dtype detect
    count_kernel<<<nblkE, TB>>>(ei);
    scan1_kernel<<<nscan, TB>>>();
    scan3_kernel<<<nblkN, TB>>>();             // prefix + dinv + seed hA + cleanup
    scatter_kernel<<<nblkE, TB>>>(ei);

    // 64 fused layers (ping-pong: A -> B -> A -> ...); first is launch #6
    int sel_in = 1;
    for (int l = 0; l < NLAYER; l++) {
        float beta = logf(THETA / (float)(l + 1) + 1.0f);
        int sel_out = 3 - sel_in;
        layer_kernel<<<nrowblk, TB>>>(convW + (size_t)l * HID * HID, beta, sel_in, sel_out);
        sel_in = sel_out;
    }

    // logits + log_softmax (l=63 wrote buffer A -> sel_in==1)
    out_kernel<<<(NN + 7) / 8, TB>>>(sel_in, W2, b2, out);
}

// round 9
// speedup vs baseline: 1.6354x; 1.0018x over previous
#include <cuda_runtime.h>
#include <cuda_fp16.h>
#include <math.h>

// ---------------- problem constants (fixed-shape problem) ----------------
#define NN 100000
#define EE 3200000
#define F_IN 128
#define HID 64
#define NLAYER 64
#define NCLASS 47
#define ALPHA 0.1f
#define THETA 0.5f

// ---------------- scratch (static device globals; no allocation) ---------
// Feature buffers hold PRE-SCALED rows:  hhat = dinv[r] * h[r]  (fp16).
// Row NN is a phantom all-zero row used to pad edge-chunk tails.
__device__ __align__(16) float  g_x0[NN * HID];          // relu(x@W1+b1), fp32
__device__ __align__(16) __half g_hA[(NN + 1) * HID];    // ping
__device__ __align__(16) __half g_hB[(NN + 1) * HID];    // pong
__device__ int   g_col[EE];          // CSR column indices
__device__ int   g_rowptr[NN + 1];
__device__ int   g_cnt[NN];          // zero at load; self-cleaned each run
__device__ int   g_cursor[NN];
__device__ float g_dinv[NN];         // 1/sqrt(deg+1)
__device__ float g_rdinv[NN];        // sqrt(deg+1)
__device__ int   g_bsum[128];
__device__ int   g_is64;

__device__ __forceinline__ const __half* pick_half(int s) {
    return (s == 1) ? g_hA : g_hB;
}
__device__ __forceinline__ __half* pick_half_mut(int s) {
    return (s == 1) ? g_hA : g_hB;
}

// packed f32x2 fma: d = a*b + d
__device__ __forceinline__ void fma2(unsigned long long& d,
                                     unsigned long long a,
                                     unsigned long long b) {
    asm("fma.rn.f32x2 %0, %1, %2, %0;" : "+l"(d) : "l"(a), "l"(b));
}

__device__ __forceinline__ int edge_at(const void* eiv, size_t idx, int is64) {
    if (is64) return (int)((const long long*)eiv)[idx];
    return ((const int*)eiv)[idx];
}

// ---------------- x0 = relu(x @ W1 + b1)  (+ inline edge-dtype detect) ----
__global__ void __launch_bounds__(256) x0_kernel(const float* __restrict__ x,
                                                 const float* __restrict__ W1,
                                                 const float* __restrict__ b1,
                                                 const unsigned int* __restrict__ eip) {
    if (blockIdx.x == 0 && threadIdx.x == 0) {
        // int64 little-endian with values < 2^32 -> odd words all zero
        int all0 = 1;
        for (int i = 0; i < 64; i++) {
            if (eip[2 * i + 1] != 0u) { all0 = 0; break; }
        }
        g_is64 = all0;
    }

    __shared__ __align__(16) float Ws[F_IN * HID];  // 32KB
    int tid = threadIdx.x;
    const float4* W4 = (const float4*)W1;
    float4* Ws4 = (float4*)Ws;
#pragma unroll
    for (int i = tid; i < (F_IN * HID) / 4; i += 256) Ws4[i] = W4[i];
    __syncthreads();

    int base = blockIdx.x * 64;
    int w = tid >> 5, lane = tid & 31;
    float bx = b1[2 * lane], by = b1[2 * lane + 1];
#pragma unroll 1
    for (int i = 0; i < 8; i++) {
        int r = base + w * 8 + i;
        if (r >= NN) continue;
        float ax = bx, ay = by;
        const float4* xr = (const float4*)(x + (size_t)r * F_IN);
#pragma unroll 8
        for (int kk = 0; kk < F_IN / 4; kk++) {
            float4 xv = xr[kk];
            int k = kk * 4;
            float2 w0 = ((const float2*)(Ws + (k + 0) * HID))[lane];
            float2 w1 = ((const float2*)(Ws + (k + 1) * HID))[lane];
            float2 w2 = ((const float2*)(Ws + (k + 2) * HID))[lane];
            float2 w3 = ((const float2*)(Ws + (k + 3) * HID))[lane];
            ax += xv.x * w0.x; ay += xv.x * w0.y;
            ax += xv.y * w1.x; ay += xv.y * w1.y;
            ax += xv.z * w2.x; ay += xv.z * w2.y;
            ax += xv.w * w3.x; ay += xv.w * w3.y;
        }
        float vx = fmaxf(ax, 0.f), vy = fmaxf(ay, 0.f);
        ((float2*)(g_x0 + (size_t)r * HID))[lane] = make_float2(vx, vy);
    }
}

// ---------------- CSR: count ----------------
__global__ void count_kernel(const void* __restrict__ eiv) {
    int i = blockIdx.x * blockDim.x + threadIdx.x;
    int is64 = g_is64;
    if (i < EE) {
        int dst = edge_at(eiv, (size_t)EE + i, is64);
        atomicAdd(&g_cnt[dst], 1);
    }
}

// ---------------- CSR: block-local exclusive scan (1024 per block) -------
__global__ void scan1_kernel() {
    __shared__ int sh[256];
    int t = threadIdx.x, b = blockIdx.x;
    int base = b * 1024 + t * 4;
    int v0 = (base + 0 < NN) ? g_cnt[base + 0] : 0;
    int v1 = (base + 1 < NN) ? g_cnt[base + 1] : 0;
    int v2 = (base + 2 < NN) ? g_cnt[base + 2] : 0;
    int v3 = (base + 3 < NN) ? g_cnt[base + 3] : 0;
    int s0 = v0, s1 = s0 + v1, s2 = s1 + v2, s3 = s2 + v3;
    sh[t] = s3;
    __syncthreads();
    for (int off = 1; off < 256; off <<= 1) {
        int v = (t >= off) ? sh[t - off] : 0;
        __syncthreads();
        sh[t] += v;
        __syncthreads();
    }
    int excl = sh[t] - s3;
    if (base + 0 < NN) g_rowptr[base + 0] = excl;
    if (base + 1 < NN) g_rowptr[base + 1] = excl + s0;
    if (base + 2 < NN) g_rowptr[base + 2] = excl + s1;
    if (base + 3 < NN) g_rowptr[base + 3] = excl + s2;
    if (t == 255) g_bsum[b] = sh[255];
}

// ---------------- CSR: finalize (inline bsum prefix) + dinv + seed hA ----
__global__ void __launch_bounds__(256) scan3_kernel() {
    __shared__ int pre_sh;
    int t = threadIdx.x, b = blockIdx.x;
    if (t == 0) {
        int nb = b >> 2;           // 1024-node block index for this 256-block
        int run = 0;
        for (int j = 0; j < nb; j++) run += g_bsum[j];
        pre_sh = run;
    }
    __syncthreads();
    int i = b * 256 + t;
    if (i < NN) {
        int rp = g_rowptr[i] + pre_sh;
        g_rowptr[i] = rp;
        g_cursor[i] = rp;
        int deg = g_cnt[i] + 1;    // +1 self loop
        float di = rsqrtf((float)deg);
        g_dinv[i] = di;
        g_rdinv[i] = sqrtf((float)deg);
        g_cnt[i] = 0;              // self-clean for next graph replay
        // seed hA with hhat0 = dinv * x0 (fp16)
        const float2* xr = (const float2*)(g_x0 + (size_t)i * HID);
        __half2* hw = (__half2*)(g_hA + (size_t)i * HID);
#pragma unroll
        for (int k = 0; k < 32; k++) {
            float2 v = xr[k];
            hw[k] = __floats2half2_rn(di * v.x, di * v.y);
        }
    }
    if (i == 0) g_rowptr[NN] = EE;
    if (b == 0 && t < 64) {        // phantom row NN = 0 in both buffers
        g_hA[(size_t)NN * HID + t] = __float2half(0.f);
        g_hB[(size_t)NN * HID + t] = __float2half(0.f);
    }
}

// ---------------- CSR: scatter ----------------
__global__ void scatter_kernel(const void* __restrict__ eiv) {
    int i = blockIdx.x * blockDim.x + threadIdx.x;
    int is64 = g_is64;
    if (i < EE) {
        int src = edge_at(eiv, (size_t)i, is64);
        int dst = edge_at(eiv, (size_t)EE + i, is64);
        int pos = atomicAdd(&g_cursor[dst], 1);
        g_col[pos] = src;
    }
}

// ---------------- fused layer --------------------------------------------
// phase 1: p[r] = dinv[r] * (sum_edges hhat[c] + hhat[r])   (pure sum!)
//          s    = (1-a)*p + a*x0
// phase 2: h = relu((1-b)s + b*(s@W));  store hhat = dinv[r]*h as fp16
__global__ void __launch_bounds__(256) layer_kernel(const float* __restrict__ Wl,
                                                    float beta, int sel_in, int sel_out) {
    __shared__ __align__(16) float Ws[HID * HID];    // 16KB
    __shared__ __align__(16) float ss[64 * 65];      // 16.6KB, pitch 65
    const __half* __restrict__ hin = pick_half(sel_in);
    __half* __restrict__ hout = pick_half_mut(sel_out);

    int tid = threadIdx.x;
    {   // stage Wl
        const float4* W4 = (const float4*)Wl;
        float4* Ws4 = (float4*)Ws;
#pragma unroll
        for (int i = tid; i < (HID * HID) / 4; i += 256) Ws4[i] = W4[i];
    }

    int base = blockIdx.x * 64;
    int w = tid >> 5, lane = tid & 31;
    int g = lane >> 4;          // edge parity group (0/1)
    int t = lane & 15;          // feature slot: features 4t..4t+3
    const unsigned FULL = 0xffffffffu;

    // -------- phase 1: warp-per-row unweighted gather --------
    // 32 cols loaded coalesced per chunk; processed in 8-edge subchunks
    // (4 pairs each, 2 edges per LDG.64), software-pipelined. Tail lanes
    // use phantom row NN (all zeros) so the loop body is branch-free.
#pragma unroll 1
    for (int i = 0; i < 8; i++) {
        int rl = w * 8 + i;
        int r = base + rl;
        if (r < NN) {
            float a0 = 0.f, a1 = 0.f, a2 = 0.f, a3 = 0.f;
            int e = g_rowptr[r];
            const int e1 = g_rowptr[r + 1];
#pragma unroll 1
            while (e < e1) {
                int rem = e1 - e;
                int cw = (lane < rem) ? g_col[e + lane] : NN;
                int np = rem < 32 ? rem : 32;
                int nsub = (np + 7) >> 3;

                uint2 ha[4];
#pragma unroll
                for (int q = 0; q < 4; q++) {
                    int idx = 2 * q + g;
                    int c = __shfl_sync(FULL, cw, idx);
                    if (idx >= np) c = NN;
                    ha[q] = ((const uint2*)(hin + (size_t)c * HID))[t];
                }
#pragma unroll 1
                for (int s = 1; s < nsub; s++) {
                    uint2 hb[4];
#pragma unroll
                    for (int q = 0; q < 4; q++) {
                        int idx = 8 * s + 2 * q + g;
                        int c = __shfl_sync(FULL, cw, idx);
                        if (idx >= np) c = NN;
                        hb[q] = ((const uint2*)(hin + (size_t)c * HID))[t];
                    }
#pragma unroll
                    for (int q = 0; q < 4; q++) {
                        float2 f0 = __half22float2(*(__half2*)&ha[q].x);
                        float2 f1 = __half22float2(*(__half2*)&ha[q].y);
                        a0 += f0.x; a1 += f0.y; a2 += f1.x; a3 += f1.y;
                        ha[q] = hb[q];
                    }
                }
#pragma unroll
                for (int q = 0; q < 4; q++) {
                    float2 f0 = __half22float2(*(__half2*)&ha[q].x);
                    float2 f1 = __half22float2(*(__half2*)&ha[q].y);
                    a0 += f0.x; a1 += f0.y; a2 += f1.x; a3 += f1.y;
                }
                e += 32;
            }
            // combine the two 16-lane halves
            a0 += __shfl_xor_sync(FULL, a0, 16);
            a1 += __shfl_xor_sync(FULL, a1, 16);
            a2 += __shfl_xor_sync(FULL, a2, 16);
            a3 += __shfl_xor_sync(FULL, a3, 16);
            // self loop: + hhat[r], then scale by dinv[r]
            uint2 hs = ((const uint2*)(hin + (size_t)r * HID))[t];
            float2 s0f = __half22float2(*(__half2*)&hs.x);
            float2 s1f = __half22float2(*(__half2*)&hs.y);
            a0 += s0f.x; a1 += s0f.y; a2 += s1f.x; a3 += s1f.y;
            float dr = g_dinv[r];
            float4 x0v = ((const float4*)(g_x0 + (size_t)r * HID))[t];
            if (lane < 16) {
                int bsh = rl * 65 + 4 * t;
                ss[bsh + 0] = (1.f - ALPHA) * (dr * a0) + ALPHA * x0v.x;
                ss[bsh + 1] = (1.f - ALPHA) * (dr * a1) + ALPHA * x0v.y;
                ss[bsh + 2] = (1.f - ALPHA) * (dr * a2) + ALPHA * x0v.z;
                ss[bsh + 3] = (1.f - ALPHA) * (dr * a3) + ALPHA * x0v.w;
            }
        }
    }
    __syncthreads();

    // -------- phase 2: 64x64 @ 64x64 GEMM from shared, packed f32x2 FMA ----
    int rl = tid & 63;
    int gq = tid >> 6;          // 4 groups of 16 columns
    int cbase = gq * 16;
    unsigned long long acc[8];
#pragma unroll
    for (int i = 0; i < 8; i++) acc[i] = 0ull;
#pragma unroll 8
    for (int k = 0; k < HID; k++) {
        float sk = ss[rl * 65 + k];
        unsigned long long skk;
        asm("mov.b64 %0, {%1, %2};" : "=l"(skk) : "f"(sk), "f"(sk));
        const ulonglong2* wp = (const ulonglong2*)(Ws + k * HID + cbase);  // warp-uniform
        ulonglong2 p0 = wp[0], p1 = wp[1], p2 = wp[2], p3 = wp[3];
        fma2(acc[0], p0.x, skk); fma2(acc[1], p0.y, skk);
        fma2(acc[2], p1.x, skk); fma2(acc[3], p1.y, skk);
        fma2(acc[4], p2.x, skk); fma2(acc[5], p2.y, skk);
        fma2(acc[6], p3.x, skk); fma2(acc[7], p3.y, skk);
    }
    int r = base + rl;
    if (r < NN) {
        float ob = 1.f - beta;
        float di = g_dinv[r];
        unsigned int u[8];
#pragma unroll
        for (int q = 0; q < 8; q++) {
            float lo, hi;
            asm("mov.b64 {%0, %1}, %2;" : "=f"(lo), "=f"(hi) : "l"(acc[q]));
            float v0 = fmaxf(ob * ss[rl * 65 + cbase + 2 * q + 0] + beta * lo, 0.f);
            float v1 = fmaxf(ob * ss[rl * 65 + cbase + 2 * q + 1] + beta * hi, 0.f);
            __half2 h2 = __floats2half2_rn(di * v0, di * v1);
            u[q] = *(unsigned int*)&h2;
        }
        uint4* dst = (uint4*)(hout + (size_t)r * HID + cbase);  // 32B-aligned
        dst[0] = make_uint4(u[0], u[1], u[2], u[3]);
        dst[1] = make_uint4(u[4], u[5], u[6], u[7]);
    }
}

// ---------------- logits + log_softmax ----------------
__global__ void __launch_bounds__(256) out_kernel(int sel_in,
                                                  const float* __restrict__ W2,
                                                  const float* __restrict__ b2,
                                                  float* __restrict__ out) {
    __shared__ float W2s[HID * NCLASS];
    __shared__ float b2s[NCLASS];
    __shared__ float hrow[8][HID];
    const __half* __restrict__ hin = pick_half(sel_in);

    int tid = threadIdx.x;
    for (int i = tid; i < HID * NCLASS; i += 256) W2s[i] = W2[i];
    if (tid < NCLASS) b2s[tid] = b2[tid];
    __syncthreads();

    int w = tid >> 5, lane = tid & 31;
    int r = blockIdx.x * 8 + w;
    if (r < NN) {
        float rdi = g_rdinv[r];   // undo the dinv pre-scaling
        hrow[w][lane] = rdi * __half2float(hin[(size_t)r * HID + lane]);
        hrow[w][lane + 32] = rdi * __half2float(hin[(size_t)r * HID + lane + 32]);
    }
    __syncwarp();
    if (r >= NN) return;

    int j0 = lane, j1 = lane + 32;
    bool has1 = (j1 < NCLASS);
    float a0 = b2s[j0];
    float a1 = has1 ? b2s[j1] : 0.f;
#pragma unroll 4
    for (int k = 0; k < HID; k++) {
        float hv = hrow[w][k];
        a0 += hv * W2s[k * NCLASS + j0];
        if (has1) a1 += hv * W2s[k * NCLASS + j1];
    }
    float m = a0;
    if (has1) m = fmaxf(m, a1);
#pragma unroll
    for (int off = 16; off; off >>= 1) m = fmaxf(m, __shfl_xor_sync(0xffffffffu, m, off));
    float s = expf(a0 - m) + (has1 ? expf(a1 - m) : 0.f);
#pragma unroll
    for (int off = 16; off; off >>= 1) s += __shfl_xor_sync(0xffffffffu, s, off);
    float lse = m + logf(s);
    out[(size_t)r * NCLASS + j0] = a0 - lse;
    if (has1) out[(size_t)r * NCLASS + j1] = a1 - lse;
}

// ---------------- launch ----------------
extern "C" void kernel_launch(void* const* d_in, const int* in_sizes, int n_in,
                              void* d_out, int out_size) {
    const float* x = (const float*)d_in[0];
    const void* ei = (const void*)d_in[1];
    const float* W1 = (const float*)d_in[2];
    const float* b1 = (const float*)d_in[3];
    const float* convW = (const float*)d_in[4];
    const float* W2 = (const float*)d_in[5];
    const float* b2 = (const float*)d_in[6];
    float* out = (float*)d_out;

    const int TB = 256;
    const int nblkN = (NN + TB - 1) / TB;      // 391
    const int nblkE = (EE + TB - 1) / TB;
    const int nscan = (NN + 1023) / 1024;      // 98
    const int nrowblk = (NN + 63) / 64;        // 1563

    // 5 preamble launches (g_cnt is zero at load and self-cleaned by scan3)
    x0_kernel<<<nrowblk, TB>>>(x, W1, b1, (const unsigned int*)ei);  // + dtype detect
    count_kernel<<<nblkE, TB>>>(ei);
    scan1_kernel<<<nscan, TB>>>();
    scan3_kernel<<<nblkN, TB>>>();             // prefix + dinv + seed hA + cleanup
    scatter_kernel<<<nblkE, TB>>>(ei);

    // 64 fused layers (ping-pong: A -> B -> A -> ...); first is launch #6
    int sel_in = 1;
    for (int l = 0; l < NLAYER; l++) {
        float beta = logf(THETA / (float)(l + 1) + 1.0f);
        int sel_out = 3 - sel_in;
        layer_kernel<<<nrowblk, TB>>>(convW + (size_t)l * HID * HID, beta, sel_in, sel_out);
        sel_in = sel_out;
    }

    // logits + log_softmax (l=63 wrote buffer A -> sel_in==1)
    out_kernel<<<(NN + 7) / 8, TB>>>(sel_in, W2, b2, out);
}